// round 1
// baseline (speedup 1.0000x reference)
#include <cuda_runtime.h>
#include <math.h>

// ---------------- model constants ----------------
#define DMODEL 512
#define NTOK   2048
#define NWIN   16
#define WSZ    128
#define NHEAD  8
#define DHEAD  64
#define FFDIM  2048

// ---------------- scratch (no allocs allowed) ----------------
__device__ alignas(128) float g_X  [NTOK * DMODEL];
__device__ alignas(128) float g_XN [NTOK * DMODEL];
__device__ alignas(128) float g_Q  [NTOK * DMODEL];
__device__ alignas(128) float g_K  [NTOK * DMODEL];
__device__ alignas(128) float g_KVX[NTOK * 2 * DMODEL];
__device__ alignas(128) float g_H  [NTOK * FFDIM];
__device__ alignas(128) float g_AO [NTOK * DMODEL];
__device__ alignas(128) float g_G  [NWIN * DMODEL];
__device__ alignas(128) float g_GN [NWIN * DMODEL];
__device__ alignas(128) float g_QG [NWIN * DMODEL];
__device__ alignas(128) float g_KVG[NWIN * 2 * DMODEL];
__device__ alignas(128) float g_GO [NWIN * DMODEL];
__device__ alignas(128) float g_GH [NWIN * FFDIM];
__device__ alignas(128) float g_GKV[NWIN * 2 * DMODEL];

// ---------------- embedding gather ----------------
__global__ void embed_kernel(const int* __restrict__ tokens,
                             const float* __restrict__ emb,
                             float* __restrict__ X)
{
    int row = blockIdx.x;            // 0..2047
    int d   = threadIdx.x;           // 0..511
    X[row * DMODEL + d] = emb[(size_t)tokens[row] * DMODEL + d];
}

// ---------------- window mean + pos emb ----------------
__global__ void winmean_kernel(const float* __restrict__ X,
                               const float* __restrict__ gpos,
                               float* __restrict__ G)
{
    int w = blockIdx.x;              // 0..15
    int d = threadIdx.x;             // 0..511
    float s = 0.f;
    for (int i = 0; i < WSZ; i++)
        s += X[(w * WSZ + i) * DMODEL + d];
    G[w * DMODEL + d] = s * (1.f / 128.f) + gpos[w * DMODEL + d];
}

// ---------------- layernorm (one block per row, 256 threads, 512 cols) ----------------
__global__ void ln_kernel(const float* __restrict__ in, float* __restrict__ out,
                          const float* __restrict__ w, const float* __restrict__ b)
{
    __shared__ float sh[8];
    __shared__ float stat;
    int row = blockIdx.x;
    int tid = threadIdx.x;
    const float* r = in + (size_t)row * DMODEL;
    float x0 = r[tid], x1 = r[tid + 256];

    float v = x0 + x1;
    for (int o = 16; o; o >>= 1) v += __shfl_down_sync(0xffffffffu, v, o);
    if ((tid & 31) == 0) sh[tid >> 5] = v;
    __syncthreads();
    if (tid == 0) {
        float t = 0.f;
        for (int i = 0; i < 8; i++) t += sh[i];
        stat = t * (1.f / 512.f);
    }
    __syncthreads();
    float mu = stat;
    float d0 = x0 - mu, d1 = x1 - mu;
    __syncthreads();           // protect sh reuse
    v = d0 * d0 + d1 * d1;
    for (int o = 16; o; o >>= 1) v += __shfl_down_sync(0xffffffffu, v, o);
    if ((tid & 31) == 0) sh[tid >> 5] = v;
    __syncthreads();
    if (tid == 0) {
        float t = 0.f;
        for (int i = 0; i < 8; i++) t += sh[i];
        stat = t * (1.f / 512.f);
    }
    __syncthreads();
    float rstd = rsqrtf(stat + 1e-5f);
    out[(size_t)row * DMODEL + tid]       = d0 * rstd * w[tid]       + b[tid];
    out[(size_t)row * DMODEL + tid + 256] = d1 * rstd * w[tid + 256] + b[tid + 256];
}

// ---------------- generic SGEMM: C = [res +] maybe_gelu(A@B + bias) ----------------
// A: [M,K] row-major (lda=K). B: [K,N] with row stride ldb. C,res: [M,N] (ldc=N).
// Requires N % 128 == 0, K % 8 == 0 (true for all call sites). M guarded.
__global__ void sgemm_kernel(const float* __restrict__ A, const float* __restrict__ B,
                             float* __restrict__ C,
                             const float* __restrict__ bias,
                             const float* __restrict__ res,
                             int M, int N, int K, int ldb, int gelu_flag)
{
    __shared__ float As[8][128];
    __shared__ float Bs[8][128];
    const int tid   = threadIdx.x;             // 256 threads
    const int crow0 = blockIdx.y * 128;
    const int ccol0 = blockIdx.x * 128;
    const int trow  = (tid / 16) * 8;
    const int tcol  = (tid % 16) * 8;

    const int arow = tid >> 1;                 // 0..127
    const int acol = (tid & 1) * 4;            // 0 or 4
    const int brow = tid >> 5;                 // 0..7
    const int bcol = (tid & 31) * 4;           // 0..124

    float acc[8][8] = {};

    for (int kt = 0; kt < K; kt += 8) {
        float4 av;
        if (crow0 + arow < M)
            av = *reinterpret_cast<const float4*>(A + (size_t)(crow0 + arow) * K + kt + acol);
        else
            av = make_float4(0.f, 0.f, 0.f, 0.f);
        As[acol + 0][arow] = av.x;
        As[acol + 1][arow] = av.y;
        As[acol + 2][arow] = av.z;
        As[acol + 3][arow] = av.w;

        float4 bv = *reinterpret_cast<const float4*>(B + (size_t)(kt + brow) * ldb + ccol0 + bcol);
        *reinterpret_cast<float4*>(&Bs[brow][bcol]) = bv;
        __syncthreads();

#pragma unroll
        for (int k = 0; k < 8; k++) {
            float ra[8], rb[8];
#pragma unroll
            for (int i = 0; i < 8; i++) ra[i] = As[k][trow + i];
#pragma unroll
            for (int j = 0; j < 8; j++) rb[j] = Bs[k][tcol + j];
#pragma unroll
            for (int i = 0; i < 8; i++)
#pragma unroll
                for (int j = 0; j < 8; j++)
                    acc[i][j] = fmaf(ra[i], rb[j], acc[i][j]);
        }
        __syncthreads();
    }

#pragma unroll
    for (int i = 0; i < 8; i++) {
        int gr = crow0 + trow + i;
        if (gr >= M) break;
#pragma unroll
        for (int j = 0; j < 8; j++) {
            int gc = ccol0 + tcol + j;
            float v = acc[i][j];
            if (bias) v += bias[gc];
            if (gelu_flag) v = 0.5f * v * (1.f + erff(v * 0.70710678118654752f));
            size_t idx = (size_t)gr * N + gc;
            if (res) v += res[idx];
            C[idx] = v;
        }
    }
}

// ---------------- rotary embedding, in-place on Q and K ----------------
__global__ void rotary_kernel(float* __restrict__ Q, float* __restrict__ K)
{
    int i = blockIdx.x;              // token position 0..2047
    int t = threadIdx.x;             // 256: h = t>>5, d = t&31
    int h = t >> 5, d = t & 31;
    float inv = 1.f / powf(10000.f, (float)(2 * d) / 64.f);
    float ang = (float)i * inv;
    float s, c;
    sincosf(ang, &s, &c);
    int base = i * DMODEL + h * DHEAD + d;
    float a = Q[base], b2 = Q[base + 32];
    Q[base]      = a * c - b2 * s;
    Q[base + 32] = b2 * c + a * s;
    a = K[base]; b2 = K[base + 32];
    K[base]      = a * c - b2 * s;
    K[base + 32] = b2 * c + a * s;
}

// ---------------- global-token attention (1 query, 129 keys per (w,h)) ----------------
__global__ void global_attn_kernel(const float* __restrict__ QG,
                                   const float* __restrict__ KVG,
                                   const float* __restrict__ KVX,
                                   float* __restrict__ GO)
{
    __shared__ float q[64];
    __shared__ float lg[129];
    int w = blockIdx.x, h = blockIdx.y;
    int tid = threadIdx.x;           // 256
    if (tid < 64) q[tid] = QG[w * DMODEL + h * DHEAD + tid];
    __syncthreads();
    if (tid < 129) {
        const float* kp = (tid == 0)
            ? (KVG + (size_t)w * 1024 + h * DHEAD)
            : (KVX + (size_t)(w * WSZ + tid - 1) * 1024 + h * DHEAD);
        float dt = 0.f;
#pragma unroll
        for (int d = 0; d < 64; d++) dt = fmaf(q[d], kp[d], dt);
        lg[tid] = dt * 0.125f;
    }
    __syncthreads();
    float m = -1e30f;
    for (int j = 0; j < 129; j++) m = fmaxf(m, lg[j]);
    float s = 0.f;
    for (int j = 0; j < 129; j++) s += expf(lg[j] - m);
    if (tid < 64) {
        float acc = 0.f;
        for (int j = 0; j < 129; j++) {
            float p = expf(lg[j] - m);
            float v = (j == 0)
                ? KVG[(size_t)w * 1024 + 512 + h * DHEAD + tid]
                : KVX[(size_t)(w * WSZ + j - 1) * 1024 + 512 + h * DHEAD + tid];
            acc = fmaf(p, v, acc);
        }
        GO[w * DMODEL + h * DHEAD + tid] = acc / s;
    }
}

// ---------------- local windowed attention with global KV ----------------
// block (w,h), 128 threads (one per query row). 271 keys:
//   j in [0,15): global keys (allowed iff j < w); values sgv.
//   j in [15,271): windowed, col c=j-15 -> token (w-1)*128+c (zeros if <0, w==0 pad);
//                  allowed iff c <= i+128; values == keys (reference closure bug).
__global__ void local_attn_kernel(const float* __restrict__ Q,
                                  const float* __restrict__ K,
                                  const float* __restrict__ GKV,
                                  float* __restrict__ AO)
{
    extern __shared__ float sm[];
    float* sk  = sm;                 // [271][64]
    float* sgv = sm + 271 * 64;      // [15][64]
    int w = blockIdx.x, h = blockIdx.y;
    int tid = threadIdx.x;           // 128

    for (int idx = tid; idx < 15 * 64; idx += 128) {
        int j = idx >> 6, d = idx & 63;
        sk[idx]  = GKV[(size_t)j * 1024 + h * DHEAD + d];
        sgv[idx] = GKV[(size_t)j * 1024 + 512 + h * DHEAD + d];
    }
    for (int idx = tid; idx < 256 * 64; idx += 128) {
        int c = idx >> 6, d = idx & 63;
        int t = (w - 1) * WSZ + c;
        sk[15 * 64 + idx] = (t >= 0) ? K[(size_t)t * DMODEL + h * DHEAD + d] : 0.f;
    }
    __syncthreads();

    const int i = tid;               // query row in window
    float q[64];
    const float* qp = Q + (size_t)(w * WSZ + i) * DMODEL + h * DHEAD;
#pragma unroll
    for (int d = 0; d < 64; d++) q[d] = qp[d];

    const int jend = 15 + i + 128;   // inclusive last windowed key

    // pass 1: max logit
    float m = -1e30f;
    for (int j = 0; j < w; j++) {
        const float* kp = sk + j * 64;
        float dt = 0.f;
#pragma unroll
        for (int d = 0; d < 64; d++) dt = fmaf(q[d], kp[d], dt);
        m = fmaxf(m, dt * 0.125f);
    }
    for (int j = 15; j <= jend; j++) {
        const float* kp = sk + j * 64;
        float dt = 0.f;
#pragma unroll
        for (int d = 0; d < 64; d++) dt = fmaf(q[d], kp[d], dt);
        m = fmaxf(m, dt * 0.125f);
    }

    // pass 2: exp-sum + weighted value accumulation
    float s = 0.f;
    float acc[64];
#pragma unroll
    for (int d = 0; d < 64; d++) acc[d] = 0.f;
    for (int j = 0; j < w; j++) {
        const float* kp = sk + j * 64;
        float dt = 0.f;
#pragma unroll
        for (int d = 0; d < 64; d++) dt = fmaf(q[d], kp[d], dt);
        float e = expf(dt * 0.125f - m);
        s += e;
        const float* vp = sgv + j * 64;
#pragma unroll
        for (int d = 0; d < 64; d++) acc[d] = fmaf(e, vp[d], acc[d]);
    }
    for (int j = 15; j <= jend; j++) {
        const float* kp = sk + j * 64;
        float dt = 0.f;
#pragma unroll
        for (int d = 0; d < 64; d++) dt = fmaf(q[d], kp[d], dt);
        float e = expf(dt * 0.125f - m);
        s += e;
#pragma unroll
        for (int d = 0; d < 64; d++) acc[d] = fmaf(e, kp[d], acc[d]);
    }
    float inv = 1.f / s;
    float* op = AO + (size_t)(w * WSZ + i) * DMODEL + h * DHEAD;
#pragma unroll
    for (int d = 0; d < 64; d++) op[d] = acc[d] * inv;
}

// ---------------- host orchestration ----------------
static inline dim3 gg(int M, int N) { return dim3(N / 128, (M + 127) / 128); }

extern "C" void kernel_launch(void* const* d_in, const int* in_sizes, int n_in,
                              void* d_out, int out_size)
{
    const int*   tokens     = (const int*)  d_in[0];
    const float* tok_emb    = (const float*)d_in[1];
    const float* gpos_emb   = (const float*)d_in[2];
    const float* g_norm_w   = (const float*)d_in[3];
    const float* g_norm_b   = (const float*)d_in[4];
    const float* g_Wq       = (const float*)d_in[5];
    const float* g_Wkv      = (const float*)d_in[6];
    const float* g_Wo       = (const float*)d_in[7];
    const float* g_bo       = (const float*)d_in[8];
    const float* gff_norm_w = (const float*)d_in[9];
    const float* gff_norm_b = (const float*)d_in[10];
    const float* gff_W1     = (const float*)d_in[11];
    const float* gff_b1     = (const float*)d_in[12];
    const float* gff_W2     = (const float*)d_in[13];
    const float* gff_b2     = (const float*)d_in[14];
    const float* la_norm_w  = (const float*)d_in[15];
    const float* la_norm_b  = (const float*)d_in[16];
    const float* la_Wq      = (const float*)d_in[17];
    const float* la_Wkv     = (const float*)d_in[18];
    const float* la_Wo      = (const float*)d_in[19];
    const float* la_bo      = (const float*)d_in[20];
    const float* lff_norm_w = (const float*)d_in[21];
    const float* lff_norm_b = (const float*)d_in[22];
    const float* lff_W1     = (const float*)d_in[23];
    const float* lff_b1     = (const float*)d_in[24];
    const float* lff_W2     = (const float*)d_in[25];
    const float* lff_b2     = (const float*)d_in[26];
    const float* out_norm_w = (const float*)d_in[27];
    const float* out_norm_b = (const float*)d_in[28];
    const float* out_W      = (const float*)d_in[29];
    const float* out_b      = (const float*)d_in[30];

    float *X, *XN, *Q, *K, *KVX, *H, *AO, *G, *GN, *QG, *KVG, *GO, *GH, *GKV;
    cudaGetSymbolAddress((void**)&X,   g_X);
    cudaGetSymbolAddress((void**)&XN,  g_XN);
    cudaGetSymbolAddress((void**)&Q,   g_Q);
    cudaGetSymbolAddress((void**)&K,   g_K);
    cudaGetSymbolAddress((void**)&KVX, g_KVX);
    cudaGetSymbolAddress((void**)&H,   g_H);
    cudaGetSymbolAddress((void**)&AO,  g_AO);
    cudaGetSymbolAddress((void**)&G,   g_G);
    cudaGetSymbolAddress((void**)&GN,  g_GN);
    cudaGetSymbolAddress((void**)&QG,  g_QG);
    cudaGetSymbolAddress((void**)&KVG, g_KVG);
    cudaGetSymbolAddress((void**)&GO,  g_GO);
    cudaGetSymbolAddress((void**)&GH,  g_GH);
    cudaGetSymbolAddress((void**)&GKV, g_GKV);

    cudaFuncSetAttribute(local_attn_kernel,
                         cudaFuncAttributeMaxDynamicSharedMemorySize, 73216);

    embed_kernel<<<NTOK, DMODEL>>>(tokens, tok_emb, X);
    winmean_kernel<<<NWIN, DMODEL>>>(X, gpos_emb, G);

    for (int l = 0; l < 2; l++) {
        // ---- global-token transformer (shared weights) ----
        ln_kernel<<<NWIN, 256>>>(G, GN, g_norm_w, g_norm_b);
        sgemm_kernel<<<gg(16, 512),  256>>>(GN, g_Wq,  QG,  nullptr, nullptr, 16,   512,  512, 512,  0);
        sgemm_kernel<<<gg(16, 1024), 256>>>(GN, g_Wkv, KVG, nullptr, nullptr, 16,   1024, 512, 1024, 0);
        sgemm_kernel<<<gg(2048,1024),256>>>(X,  g_Wkv, KVX, nullptr, nullptr, 2048, 1024, 512, 1024, 0);
        global_attn_kernel<<<dim3(16, 8), 256>>>(QG, KVG, KVX, GO);
        sgemm_kernel<<<gg(16, 512),  256>>>(GO, g_Wo, G, g_bo, G, 16, 512, 512, 512, 0);
        ln_kernel<<<NWIN, 256>>>(G, GN, gff_norm_w, gff_norm_b);
        sgemm_kernel<<<gg(16, 2048), 256>>>(GN, gff_W1, GH, gff_b1, nullptr, 16, 2048, 512,  2048, 1);
        sgemm_kernel<<<gg(16, 512),  256>>>(GH, gff_W2, G,  gff_b2, G,       16, 512,  2048, 512,  0);

        // ---- local windowed attention ----
        ln_kernel<<<NTOK, 256>>>(X, XN, la_norm_w + l * 512, la_norm_b + l * 512);
        sgemm_kernel<<<gg(2048, 512), 256>>>(XN, la_Wq  + (size_t)l * 512 * 512,  Q,   nullptr, nullptr, 2048, 512,  512, 512,  0);
        sgemm_kernel<<<gg(2048, 512), 256>>>(XN, la_Wkv + (size_t)l * 512 * 1024, K,   nullptr, nullptr, 2048, 512,  512, 1024, 0);
        sgemm_kernel<<<gg(15, 1024),  256>>>(G,  la_Wkv + (size_t)l * 512 * 1024, GKV, nullptr, nullptr, 15,   1024, 512, 1024, 0);
        rotary_kernel<<<NTOK, 256>>>(Q, K);
        local_attn_kernel<<<dim3(16, 8), 128, 73216>>>(Q, K, GKV, AO);
        sgemm_kernel<<<gg(2048, 512), 256>>>(AO, la_Wo + (size_t)l * 512 * 512, X, la_bo + l * 512, X, 2048, 512, 512, 512, 0);

        // ---- local FF ----
        ln_kernel<<<NTOK, 256>>>(X, XN, lff_norm_w + l * 512, lff_norm_b + l * 512);
        sgemm_kernel<<<gg(2048, 2048), 256>>>(XN, lff_W1 + (size_t)l * 512 * 2048, H, lff_b1 + l * 2048, nullptr, 2048, 2048, 512,  2048, 1);
        sgemm_kernel<<<gg(2048, 512),  256>>>(H,  lff_W2 + (size_t)l * 2048 * 512, X, lff_b2 + l * 512,  X,       2048, 512,  2048, 512,  0);
    }

    // ---- output head ----
    ln_kernel<<<NTOK, 256>>>(X, XN, out_norm_w, out_norm_b);
    sgemm_kernel<<<gg(2048, 32000), 256>>>(XN, out_W, (float*)d_out, out_b, nullptr,
                                           2048, 32000, 512, 32000, 0);
}

// round 2
// speedup vs baseline: 1.7472x; 1.7472x over previous
#include <cuda_runtime.h>
#include <math.h>
#include <stdint.h>

// ---------------- model constants ----------------
#define DMODEL 512
#define NTOK   2048
#define NWIN   16
#define WSZ    128
#define NHEAD  8
#define DHEAD  64
#define FFDIM  2048

// ---------------- scratch (no allocs allowed) ----------------
__device__ alignas(128) float g_X  [NTOK * DMODEL];
__device__ alignas(128) float g_XN [NTOK * DMODEL];
__device__ alignas(128) float g_Q  [NTOK * DMODEL];
__device__ alignas(128) float g_K  [NTOK * DMODEL];
__device__ alignas(128) float g_KVX[NTOK * 2 * DMODEL];
__device__ alignas(128) float g_H  [NTOK * FFDIM];
__device__ alignas(128) float g_AO [NTOK * DMODEL];
__device__ alignas(128) float g_G  [NWIN * DMODEL];
__device__ alignas(128) float g_GN [NWIN * DMODEL];
__device__ alignas(128) float g_QG [NWIN * DMODEL];
__device__ alignas(128) float g_KVG[NWIN * 2 * DMODEL];
__device__ alignas(128) float g_GO [NWIN * DMODEL];
__device__ alignas(128) float g_GH [NWIN * FFDIM];
__device__ alignas(128) float g_GKV[NWIN * 2 * DMODEL];

// ---------------- embedding gather ----------------
__global__ void embed_kernel(const int* __restrict__ tokens,
                             const float* __restrict__ emb,
                             float* __restrict__ X)
{
    int row = blockIdx.x;
    int d   = threadIdx.x;
    X[row * DMODEL + d] = emb[(size_t)tokens[row] * DMODEL + d];
}

// ---------------- window mean + pos emb ----------------
__global__ void winmean_kernel(const float* __restrict__ X,
                               const float* __restrict__ gpos,
                               float* __restrict__ G)
{
    int w = blockIdx.x;
    int d = threadIdx.x;
    float s = 0.f;
    for (int i = 0; i < WSZ; i++)
        s += X[(w * WSZ + i) * DMODEL + d];
    G[w * DMODEL + d] = s * (1.f / 128.f) + gpos[w * DMODEL + d];
}

// ---------------- layernorm ----------------
__global__ void ln_kernel(const float* __restrict__ in, float* __restrict__ out,
                          const float* __restrict__ w, const float* __restrict__ b)
{
    __shared__ float sh[8];
    __shared__ float stat;
    int row = blockIdx.x;
    int tid = threadIdx.x;
    const float* r = in + (size_t)row * DMODEL;
    float x0 = r[tid], x1 = r[tid + 256];

    float v = x0 + x1;
    for (int o = 16; o; o >>= 1) v += __shfl_down_sync(0xffffffffu, v, o);
    if ((tid & 31) == 0) sh[tid >> 5] = v;
    __syncthreads();
    if (tid == 0) {
        float t = 0.f;
        for (int i = 0; i < 8; i++) t += sh[i];
        stat = t * (1.f / 512.f);
    }
    __syncthreads();
    float mu = stat;
    float d0 = x0 - mu, d1 = x1 - mu;
    __syncthreads();
    v = d0 * d0 + d1 * d1;
    for (int o = 16; o; o >>= 1) v += __shfl_down_sync(0xffffffffu, v, o);
    if ((tid & 31) == 0) sh[tid >> 5] = v;
    __syncthreads();
    if (tid == 0) {
        float t = 0.f;
        for (int i = 0; i < 8; i++) t += sh[i];
        stat = t * (1.f / 512.f);
    }
    __syncthreads();
    float rstd = rsqrtf(stat + 1e-5f);
    out[(size_t)row * DMODEL + tid]       = d0 * rstd * w[tid]       + b[tid];
    out[(size_t)row * DMODEL + tid + 256] = d1 * rstd * w[tid + 256] + b[tid + 256];
}

// ---------------- tf32 helpers ----------------
__device__ __forceinline__ float to_tf32(float x)
{
    float r;
    asm("cvt.rna.tf32.f32 %0, %1;" : "=f"(r) : "f"(x));
    return r;
}

__device__ __forceinline__ void mma_tf32(float* c, const uint32_t* a, const uint32_t* b)
{
    asm volatile(
        "mma.sync.aligned.m16n8k8.row.col.f32.tf32.tf32.f32 "
        "{%0,%1,%2,%3}, {%4,%5,%6,%7}, {%8,%9}, {%0,%1,%2,%3};"
        : "+f"(c[0]), "+f"(c[1]), "+f"(c[2]), "+f"(c[3])
        : "r"(a[0]), "r"(a[1]), "r"(a[2]), "r"(a[3]), "r"(b[0]), "r"(b[1]));
}

// ---------------- tf32 tensor-core GEMM ----------------
// C[M,N] = [res +] maybe_gelu(A@B + bias). A:[M,K] lda=K. B row stride ldb.
// Requires M%128==0, N%128==0, K%16==0.
// 128x128 block tile, ktile 16, 8 warps each 64x32 (4x4 m16n8k8 atoms).
// Smem stride 136 floats (==8 mod 32) -> conflict-free fragment LDS.
#define KT 16
#define SMS 136
__global__ void __launch_bounds__(256, 2) tf32gemm_kernel(
    const float* __restrict__ A, const float* __restrict__ B, float* __restrict__ C,
    const float* __restrict__ bias, const float* __restrict__ res,
    int M, int N, int K, int ldb, int gelu_flag)
{
    __shared__ float As[2][KT][SMS];   // [k][m]
    __shared__ float Bs[2][KT][SMS];   // [k][n]

    const int tid  = threadIdx.x;
    const int lane = tid & 31, warp = tid >> 5;
    const int wm = (warp & 1) * 64;    // warp row offset in tile
    const int wn = (warp >> 1) * 32;   // warp col offset in tile
    const int crow0 = blockIdx.y * 128, ccol0 = blockIdx.x * 128;

    // global load mapping: A 128x16 (8 floats/thread), B 16x128 (8 floats/thread)
    const int a_r = tid >> 1, a_c = (tid & 1) * 8;
    const int b_r = tid >> 4, b_c = (tid & 15) * 8;

    const float* Ag = A + (size_t)(crow0 + a_r) * K + a_c;
    const float* Bg = B + (size_t)b_r * ldb + ccol0 + b_c;

    float acc[4][4][4];
#pragma unroll
    for (int i = 0; i < 4; i++)
#pragma unroll
        for (int j = 0; j < 4; j++)
#pragma unroll
            for (int k = 0; k < 4; k++) acc[i][j][k] = 0.f;

    const int nk = K / KT;

    // preload tile 0
    {
        float4 av0 = *reinterpret_cast<const float4*>(Ag);
        float4 av1 = *reinterpret_cast<const float4*>(Ag + 4);
        float4 bv0 = *reinterpret_cast<const float4*>(Bg);
        float4 bv1 = *reinterpret_cast<const float4*>(Bg + 4);
        As[0][a_c + 0][a_r] = to_tf32(av0.x);
        As[0][a_c + 1][a_r] = to_tf32(av0.y);
        As[0][a_c + 2][a_r] = to_tf32(av0.z);
        As[0][a_c + 3][a_r] = to_tf32(av0.w);
        As[0][a_c + 4][a_r] = to_tf32(av1.x);
        As[0][a_c + 5][a_r] = to_tf32(av1.y);
        As[0][a_c + 6][a_r] = to_tf32(av1.z);
        As[0][a_c + 7][a_r] = to_tf32(av1.w);
        float4 t0 = make_float4(to_tf32(bv0.x), to_tf32(bv0.y), to_tf32(bv0.z), to_tf32(bv0.w));
        float4 t1 = make_float4(to_tf32(bv1.x), to_tf32(bv1.y), to_tf32(bv1.z), to_tf32(bv1.w));
        *reinterpret_cast<float4*>(&Bs[0][b_r][b_c])     = t0;
        *reinterpret_cast<float4*>(&Bs[0][b_r][b_c + 4]) = t1;
    }
    __syncthreads();

    for (int kt = 0; kt < nk; kt++) {
        const int cur = kt & 1, nxt = cur ^ 1;

        float4 av0, av1, bv0, bv1;
        const bool more = (kt + 1 < nk);
        if (more) {
            const float* Ap = Ag + (kt + 1) * KT;
            const float* Bp = Bg + (size_t)(kt + 1) * KT * ldb;
            av0 = *reinterpret_cast<const float4*>(Ap);
            av1 = *reinterpret_cast<const float4*>(Ap + 4);
            bv0 = *reinterpret_cast<const float4*>(Bp);
            bv1 = *reinterpret_cast<const float4*>(Bp + 4);
        }

#pragma unroll
        for (int kk = 0; kk < KT; kk += 8) {
            uint32_t af[4][4], bf[4][2];
            const int kc = kk + (lane & 3);
#pragma unroll
            for (int am = 0; am < 4; am++) {
                const int r = wm + am * 16 + (lane >> 2);
                af[am][0] = __float_as_uint(As[cur][kc][r]);
                af[am][1] = __float_as_uint(As[cur][kc][r + 8]);
                af[am][2] = __float_as_uint(As[cur][kc + 4][r]);
                af[am][3] = __float_as_uint(As[cur][kc + 4][r + 8]);
            }
#pragma unroll
            for (int bn = 0; bn < 4; bn++) {
                const int cc = wn + bn * 8 + (lane >> 2);
                bf[bn][0] = __float_as_uint(Bs[cur][kc][cc]);
                bf[bn][1] = __float_as_uint(Bs[cur][kc + 4][cc]);
            }
#pragma unroll
            for (int am = 0; am < 4; am++)
#pragma unroll
                for (int bn = 0; bn < 4; bn++)
                    mma_tf32(acc[am][bn], af[am], bf[bn]);
        }

        if (more) {
            As[nxt][a_c + 0][a_r] = to_tf32(av0.x);
            As[nxt][a_c + 1][a_r] = to_tf32(av0.y);
            As[nxt][a_c + 2][a_r] = to_tf32(av0.z);
            As[nxt][a_c + 3][a_r] = to_tf32(av0.w);
            As[nxt][a_c + 4][a_r] = to_tf32(av1.x);
            As[nxt][a_c + 5][a_r] = to_tf32(av1.y);
            As[nxt][a_c + 6][a_r] = to_tf32(av1.z);
            As[nxt][a_c + 7][a_r] = to_tf32(av1.w);
            float4 t0 = make_float4(to_tf32(bv0.x), to_tf32(bv0.y), to_tf32(bv0.z), to_tf32(bv0.w));
            float4 t1 = make_float4(to_tf32(bv1.x), to_tf32(bv1.y), to_tf32(bv1.z), to_tf32(bv1.w));
            *reinterpret_cast<float4*>(&Bs[nxt][b_r][b_c])     = t0;
            *reinterpret_cast<float4*>(&Bs[nxt][b_r][b_c + 4]) = t1;
            __syncthreads();
        }
    }

    // epilogue
#pragma unroll
    for (int am = 0; am < 4; am++) {
        const int r0 = crow0 + wm + am * 16 + (lane >> 2);
#pragma unroll
        for (int bn = 0; bn < 4; bn++) {
            const int c0 = ccol0 + wn + bn * 8 + (lane & 3) * 2;
            float v0 = acc[am][bn][0], v1 = acc[am][bn][1];
            float v2 = acc[am][bn][2], v3 = acc[am][bn][3];
            if (bias) {
                float b0 = bias[c0], b1 = bias[c0 + 1];
                v0 += b0; v1 += b1; v2 += b0; v3 += b1;
            }
            if (gelu_flag) {
                v0 = 0.5f * v0 * (1.f + erff(v0 * 0.70710678118654752f));
                v1 = 0.5f * v1 * (1.f + erff(v1 * 0.70710678118654752f));
                v2 = 0.5f * v2 * (1.f + erff(v2 * 0.70710678118654752f));
                v3 = 0.5f * v3 * (1.f + erff(v3 * 0.70710678118654752f));
            }
            size_t i0 = (size_t)r0 * N + c0;
            size_t i1 = (size_t)(r0 + 8) * N + c0;
            if (res) {
                v0 += res[i0]; v1 += res[i0 + 1];
                v2 += res[i1]; v3 += res[i1 + 1];
            }
            *reinterpret_cast<float2*>(C + i0) = make_float2(v0, v1);
            *reinterpret_cast<float2*>(C + i1) = make_float2(v2, v3);
        }
    }
}

// ---------------- fp32 SGEMM (small-M call sites only) ----------------
__global__ void sgemm_kernel(const float* __restrict__ A, const float* __restrict__ B,
                             float* __restrict__ C,
                             const float* __restrict__ bias,
                             const float* __restrict__ res,
                             int M, int N, int K, int ldb, int gelu_flag)
{
    __shared__ float As[8][128];
    __shared__ float Bs[8][128];
    const int tid   = threadIdx.x;
    const int crow0 = blockIdx.y * 128;
    const int ccol0 = blockIdx.x * 128;
    const int trow  = (tid / 16) * 8;
    const int tcol  = (tid % 16) * 8;

    const int arow = tid >> 1;
    const int acol = (tid & 1) * 4;
    const int brow = tid >> 5;
    const int bcol = (tid & 31) * 4;

    float acc[8][8] = {};

    for (int kt = 0; kt < K; kt += 8) {
        float4 av;
        if (crow0 + arow < M)
            av = *reinterpret_cast<const float4*>(A + (size_t)(crow0 + arow) * K + kt + acol);
        else
            av = make_float4(0.f, 0.f, 0.f, 0.f);
        As[acol + 0][arow] = av.x;
        As[acol + 1][arow] = av.y;
        As[acol + 2][arow] = av.z;
        As[acol + 3][arow] = av.w;

        float4 bv = *reinterpret_cast<const float4*>(B + (size_t)(kt + brow) * ldb + ccol0 + bcol);
        *reinterpret_cast<float4*>(&Bs[brow][bcol]) = bv;
        __syncthreads();

#pragma unroll
        for (int k = 0; k < 8; k++) {
            float ra[8], rb[8];
#pragma unroll
            for (int i = 0; i < 8; i++) ra[i] = As[k][trow + i];
#pragma unroll
            for (int j = 0; j < 8; j++) rb[j] = Bs[k][tcol + j];
#pragma unroll
            for (int i = 0; i < 8; i++)
#pragma unroll
                for (int j = 0; j < 8; j++)
                    acc[i][j] = fmaf(ra[i], rb[j], acc[i][j]);
        }
        __syncthreads();
    }

#pragma unroll
    for (int i = 0; i < 8; i++) {
        int gr = crow0 + trow + i;
        if (gr >= M) break;
#pragma unroll
        for (int j = 0; j < 8; j++) {
            int gc = ccol0 + tcol + j;
            float v = acc[i][j];
            if (bias) v += bias[gc];
            if (gelu_flag) v = 0.5f * v * (1.f + erff(v * 0.70710678118654752f));
            size_t idx = (size_t)gr * N + gc;
            if (res) v += res[idx];
            C[idx] = v;
        }
    }
}

// ---------------- rotary embedding ----------------
__global__ void rotary_kernel(float* __restrict__ Q, float* __restrict__ K)
{
    int i = blockIdx.x;
    int t = threadIdx.x;
    int h = t >> 5, d = t & 31;
    float inv = 1.f / powf(10000.f, (float)(2 * d) / 64.f);
    float ang = (float)i * inv;
    float s, c;
    sincosf(ang, &s, &c);
    int base = i * DMODEL + h * DHEAD + d;
    float a = Q[base], b2 = Q[base + 32];
    Q[base]      = a * c - b2 * s;
    Q[base + 32] = b2 * c + a * s;
    a = K[base]; b2 = K[base + 32];
    K[base]      = a * c - b2 * s;
    K[base + 32] = b2 * c + a * s;
}

// ---------------- global-token attention ----------------
__global__ void global_attn_kernel(const float* __restrict__ QG,
                                   const float* __restrict__ KVG,
                                   const float* __restrict__ KVX,
                                   float* __restrict__ GO)
{
    __shared__ float q[64];
    __shared__ float lg[129];
    int w = blockIdx.x, h = blockIdx.y;
    int tid = threadIdx.x;
    if (tid < 64) q[tid] = QG[w * DMODEL + h * DHEAD + tid];
    __syncthreads();
    if (tid < 129) {
        const float* kp = (tid == 0)
            ? (KVG + (size_t)w * 1024 + h * DHEAD)
            : (KVX + (size_t)(w * WSZ + tid - 1) * 1024 + h * DHEAD);
        float dt = 0.f;
#pragma unroll
        for (int d = 0; d < 64; d++) dt = fmaf(q[d], kp[d], dt);
        lg[tid] = dt * 0.125f;
    }
    __syncthreads();
    float m = -1e30f;
    for (int j = 0; j < 129; j++) m = fmaxf(m, lg[j]);
    float s = 0.f;
    for (int j = 0; j < 129; j++) s += expf(lg[j] - m);
    if (tid < 64) {
        float acc = 0.f;
        for (int j = 0; j < 129; j++) {
            float p = expf(lg[j] - m);
            float v = (j == 0)
                ? KVG[(size_t)w * 1024 + 512 + h * DHEAD + tid]
                : KVX[(size_t)(w * WSZ + j - 1) * 1024 + 512 + h * DHEAD + tid];
            acc = fmaf(p, v, acc);
        }
        GO[w * DMODEL + h * DHEAD + tid] = acc / s;
    }
}

// ---------------- local windowed attention ----------------
__global__ void local_attn_kernel(const float* __restrict__ Q,
                                  const float* __restrict__ K,
                                  const float* __restrict__ GKV,
                                  float* __restrict__ AO)
{
    extern __shared__ float sm[];
    float* sk  = sm;                 // [271][64]
    float* sgv = sm + 271 * 64;      // [15][64]
    int w = blockIdx.x, h = blockIdx.y;
    int tid = threadIdx.x;           // 128

    for (int idx = tid; idx < 15 * 64; idx += 128) {
        int j = idx >> 6, d = idx & 63;
        sk[idx]  = GKV[(size_t)j * 1024 + h * DHEAD + d];
        sgv[idx] = GKV[(size_t)j * 1024 + 512 + h * DHEAD + d];
    }
    for (int idx = tid; idx < 256 * 64; idx += 128) {
        int c = idx >> 6, d = idx & 63;
        int t = (w - 1) * WSZ + c;
        sk[15 * 64 + idx] = (t >= 0) ? K[(size_t)t * DMODEL + h * DHEAD + d] : 0.f;
    }
    __syncthreads();

    const int i = tid;
    float q[64];
    const float* qp = Q + (size_t)(w * WSZ + i) * DMODEL + h * DHEAD;
#pragma unroll
    for (int d = 0; d < 64; d++) q[d] = qp[d];

    const int jend = 15 + i + 128;

    float m = -1e30f;
    for (int j = 0; j < w; j++) {
        const float* kp = sk + j * 64;
        float dt = 0.f;
#pragma unroll
        for (int d = 0; d < 64; d++) dt = fmaf(q[d], kp[d], dt);
        m = fmaxf(m, dt * 0.125f);
    }
    for (int j = 15; j <= jend; j++) {
        const float* kp = sk + j * 64;
        float dt = 0.f;
#pragma unroll
        for (int d = 0; d < 64; d++) dt = fmaf(q[d], kp[d], dt);
        m = fmaxf(m, dt * 0.125f);
    }

    float s = 0.f;
    float acc[64];
#pragma unroll
    for (int d = 0; d < 64; d++) acc[d] = 0.f;
    for (int j = 0; j < w; j++) {
        const float* kp = sk + j * 64;
        float dt = 0.f;
#pragma unroll
        for (int d = 0; d < 64; d++) dt = fmaf(q[d], kp[d], dt);
        float e = expf(dt * 0.125f - m);
        s += e;
        const float* vp = sgv + j * 64;
#pragma unroll
        for (int d = 0; d < 64; d++) acc[d] = fmaf(e, vp[d], acc[d]);
    }
    for (int j = 15; j <= jend; j++) {
        const float* kp = sk + j * 64;
        float dt = 0.f;
#pragma unroll
        for (int d = 0; d < 64; d++) dt = fmaf(q[d], kp[d], dt);
        float e = expf(dt * 0.125f - m);
        s += e;
#pragma unroll
        for (int d = 0; d < 64; d++) acc[d] = fmaf(e, kp[d], acc[d]);
    }
    float inv = 1.f / s;
    float* op = AO + (size_t)(w * WSZ + i) * DMODEL + h * DHEAD;
#pragma unroll
    for (int d = 0; d < 64; d++) op[d] = acc[d] * inv;
}

// ---------------- host orchestration ----------------
static inline dim3 gg(int M, int N) { return dim3(N / 128, (M + 127) / 128); }

extern "C" void kernel_launch(void* const* d_in, const int* in_sizes, int n_in,
                              void* d_out, int out_size)
{
    const int*   tokens     = (const int*)  d_in[0];
    const float* tok_emb    = (const float*)d_in[1];
    const float* gpos_emb   = (const float*)d_in[2];
    const float* g_norm_w   = (const float*)d_in[3];
    const float* g_norm_b   = (const float*)d_in[4];
    const float* g_Wq       = (const float*)d_in[5];
    const float* g_Wkv      = (const float*)d_in[6];
    const float* g_Wo       = (const float*)d_in[7];
    const float* g_bo       = (const float*)d_in[8];
    const float* gff_norm_w = (const float*)d_in[9];
    const float* gff_norm_b = (const float*)d_in[10];
    const float* gff_W1     = (const float*)d_in[11];
    const float* gff_b1     = (const float*)d_in[12];
    const float* gff_W2     = (const float*)d_in[13];
    const float* gff_b2     = (const float*)d_in[14];
    const float* la_norm_w  = (const float*)d_in[15];
    const float* la_norm_b  = (const float*)d_in[16];
    const float* la_Wq      = (const float*)d_in[17];
    const float* la_Wkv     = (const float*)d_in[18];
    const float* la_Wo      = (const float*)d_in[19];
    const float* la_bo      = (const float*)d_in[20];
    const float* lff_norm_w = (const float*)d_in[21];
    const float* lff_norm_b = (const float*)d_in[22];
    const float* lff_W1     = (const float*)d_in[23];
    const float* lff_b1     = (const float*)d_in[24];
    const float* lff_W2     = (const float*)d_in[25];
    const float* lff_b2     = (const float*)d_in[26];
    const float* out_norm_w = (const float*)d_in[27];
    const float* out_norm_b = (const float*)d_in[28];
    const float* out_W      = (const float*)d_in[29];
    const float* out_b      = (const float*)d_in[30];

    float *X, *XN, *Q, *K, *KVX, *H, *AO, *G, *GN, *QG, *KVG, *GO, *GH, *GKV;
    cudaGetSymbolAddress((void**)&X,   g_X);
    cudaGetSymbolAddress((void**)&XN,  g_XN);
    cudaGetSymbolAddress((void**)&Q,   g_Q);
    cudaGetSymbolAddress((void**)&K,   g_K);
    cudaGetSymbolAddress((void**)&KVX, g_KVX);
    cudaGetSymbolAddress((void**)&H,   g_H);
    cudaGetSymbolAddress((void**)&AO,  g_AO);
    cudaGetSymbolAddress((void**)&G,   g_G);
    cudaGetSymbolAddress((void**)&GN,  g_GN);
    cudaGetSymbolAddress((void**)&QG,  g_QG);
    cudaGetSymbolAddress((void**)&KVG, g_KVG);
    cudaGetSymbolAddress((void**)&GO,  g_GO);
    cudaGetSymbolAddress((void**)&GH,  g_GH);
    cudaGetSymbolAddress((void**)&GKV, g_GKV);

    cudaFuncSetAttribute(local_attn_kernel,
                         cudaFuncAttributeMaxDynamicSharedMemorySize, 73216);

    embed_kernel<<<NTOK, DMODEL>>>(tokens, tok_emb, X);
    winmean_kernel<<<NWIN, DMODEL>>>(X, gpos_emb, G);

    for (int l = 0; l < 2; l++) {
        // ---- global-token transformer (shared weights) ----
        ln_kernel<<<NWIN, 256>>>(G, GN, g_norm_w, g_norm_b);
        sgemm_kernel<<<gg(16, 512),  256>>>(GN, g_Wq,  QG,  nullptr, nullptr, 16,   512,  512, 512,  0);
        sgemm_kernel<<<gg(16, 1024), 256>>>(GN, g_Wkv, KVG, nullptr, nullptr, 16,   1024, 512, 1024, 0);
        tf32gemm_kernel<<<gg(2048, 1024), 256>>>(X, g_Wkv, KVX, nullptr, nullptr, 2048, 1024, 512, 1024, 0);
        global_attn_kernel<<<dim3(16, 8), 256>>>(QG, KVG, KVX, GO);
        sgemm_kernel<<<gg(16, 512),  256>>>(GO, g_Wo, G, g_bo, G, 16, 512, 512, 512, 0);
        ln_kernel<<<NWIN, 256>>>(G, GN, gff_norm_w, gff_norm_b);
        sgemm_kernel<<<gg(16, 2048), 256>>>(GN, gff_W1, GH, gff_b1, nullptr, 16, 2048, 512,  2048, 1);
        sgemm_kernel<<<gg(16, 512),  256>>>(GH, gff_W2, G,  gff_b2, G,       16, 512,  2048, 512,  0);

        // ---- local windowed attention ----
        ln_kernel<<<NTOK, 256>>>(X, XN, la_norm_w + l * 512, la_norm_b + l * 512);
        tf32gemm_kernel<<<gg(2048, 512), 256>>>(XN, la_Wq  + (size_t)l * 512 * 512,  Q, nullptr, nullptr, 2048, 512, 512, 512,  0);
        tf32gemm_kernel<<<gg(2048, 512), 256>>>(XN, la_Wkv + (size_t)l * 512 * 1024, K, nullptr, nullptr, 2048, 512, 512, 1024, 0);
        sgemm_kernel<<<gg(15, 1024), 256>>>(G, la_Wkv + (size_t)l * 512 * 1024, GKV, nullptr, nullptr, 15, 1024, 512, 1024, 0);
        rotary_kernel<<<NTOK, 256>>>(Q, K);
        local_attn_kernel<<<dim3(16, 8), 128, 73216>>>(Q, K, GKV, AO);
        tf32gemm_kernel<<<gg(2048, 512), 256>>>(AO, la_Wo + (size_t)l * 512 * 512, X, la_bo + l * 512, X, 2048, 512, 512, 512, 0);

        // ---- local FF ----
        ln_kernel<<<NTOK, 256>>>(X, XN, lff_norm_w + l * 512, lff_norm_b + l * 512);
        tf32gemm_kernel<<<gg(2048, 2048), 256>>>(XN, lff_W1 + (size_t)l * 512 * 2048, H, lff_b1 + l * 2048, nullptr, 2048, 2048, 512,  2048, 1);
        tf32gemm_kernel<<<gg(2048, 512),  256>>>(H,  lff_W2 + (size_t)l * 2048 * 512, X, lff_b2 + l * 512,  X,       2048, 512,  2048, 512,  0);
    }

    // ---- output head ----
    ln_kernel<<<NTOK, 256>>>(X, XN, out_norm_w, out_norm_b);
    tf32gemm_kernel<<<gg(2048, 32000), 256>>>(XN, out_W, (float*)d_out, out_b, nullptr,
                                              2048, 32000, 512, 32000, 0);
}

// round 3
// speedup vs baseline: 2.0745x; 1.1874x over previous
#include <cuda_runtime.h>
#include <math.h>
#include <stdint.h>

// ---------------- model constants ----------------
#define DMODEL 512
#define NTOK   2048
#define NWIN   16
#define WSZ    128
#define NHEAD  8
#define DHEAD  64
#define FFDIM  2048

// ---------------- scratch (no allocs allowed) ----------------
__device__ alignas(128) float g_X  [NTOK * DMODEL];
__device__ alignas(128) float g_XN [NTOK * DMODEL];
__device__ alignas(128) float g_Q  [NTOK * DMODEL];
__device__ alignas(128) float g_K  [NTOK * DMODEL];
__device__ alignas(128) float g_KVX[NTOK * 2 * DMODEL];
__device__ alignas(128) float g_H  [NTOK * FFDIM];
__device__ alignas(128) float g_AO [NTOK * DMODEL];
__device__ alignas(128) float g_G  [NWIN * DMODEL];
__device__ alignas(128) float g_GN [NWIN * DMODEL];
__device__ alignas(128) float g_QG [NWIN * DMODEL];
__device__ alignas(128) float g_KVG[NWIN * 2 * DMODEL];
__device__ alignas(128) float g_GO [NWIN * DMODEL];
__device__ alignas(128) float g_GH [NWIN * FFDIM];
__device__ alignas(128) float g_GKV[NWIN * 2 * DMODEL];

// ---------------- embedding gather ----------------
__global__ void embed_kernel(const int* __restrict__ tokens,
                             const float* __restrict__ emb,
                             float* __restrict__ X)
{
    int row = blockIdx.x;
    int d   = threadIdx.x;
    X[row * DMODEL + d] = emb[(size_t)tokens[row] * DMODEL + d];
}

// ---------------- window mean + pos emb ----------------
__global__ void winmean_kernel(const float* __restrict__ X,
                               const float* __restrict__ gpos,
                               float* __restrict__ G)
{
    int w = blockIdx.x;
    int d = threadIdx.x;
    float s = 0.f;
    for (int i = 0; i < WSZ; i++)
        s += X[(w * WSZ + i) * DMODEL + d];
    G[w * DMODEL + d] = s * (1.f / 128.f) + gpos[w * DMODEL + d];
}

// ---------------- layernorm ----------------
__global__ void ln_kernel(const float* __restrict__ in, float* __restrict__ out,
                          const float* __restrict__ w, const float* __restrict__ b)
{
    __shared__ float sh[8];
    __shared__ float stat;
    int row = blockIdx.x;
    int tid = threadIdx.x;
    const float* r = in + (size_t)row * DMODEL;
    float x0 = r[tid], x1 = r[tid + 256];

    float v = x0 + x1;
    for (int o = 16; o; o >>= 1) v += __shfl_down_sync(0xffffffffu, v, o);
    if ((tid & 31) == 0) sh[tid >> 5] = v;
    __syncthreads();
    if (tid == 0) {
        float t = 0.f;
        for (int i = 0; i < 8; i++) t += sh[i];
        stat = t * (1.f / 512.f);
    }
    __syncthreads();
    float mu = stat;
    float d0 = x0 - mu, d1 = x1 - mu;
    __syncthreads();
    v = d0 * d0 + d1 * d1;
    for (int o = 16; o; o >>= 1) v += __shfl_down_sync(0xffffffffu, v, o);
    if ((tid & 31) == 0) sh[tid >> 5] = v;
    __syncthreads();
    if (tid == 0) {
        float t = 0.f;
        for (int i = 0; i < 8; i++) t += sh[i];
        stat = t * (1.f / 512.f);
    }
    __syncthreads();
    float rstd = rsqrtf(stat + 1e-5f);
    out[(size_t)row * DMODEL + tid]       = d0 * rstd * w[tid]       + b[tid];
    out[(size_t)row * DMODEL + tid + 256] = d1 * rstd * w[tid + 256] + b[tid + 256];
}

// ---------------- tf32 helpers ----------------
__device__ __forceinline__ float to_tf32(float x)
{
    float r;
    asm("cvt.rna.tf32.f32 %0, %1;" : "=f"(r) : "f"(x));
    return r;
}

__device__ __forceinline__ void mma_tf32(float* c, const uint32_t* a, const uint32_t* b)
{
    asm volatile(
        "mma.sync.aligned.m16n8k8.row.col.f32.tf32.tf32.f32 "
        "{%0,%1,%2,%3}, {%4,%5,%6,%7}, {%8,%9}, {%0,%1,%2,%3};"
        : "+f"(c[0]), "+f"(c[1]), "+f"(c[2]), "+f"(c[3])
        : "r"(a[0]), "r"(a[1]), "r"(a[2]), "r"(a[3]), "r"(b[0]), "r"(b[1]));
}

// ---------------- tf32 tensor-core GEMM (M%128==0, N%128==0, K%16==0) ----------------
#define KT 16
#define SMS 136
__global__ void __launch_bounds__(256, 2) tf32gemm_kernel(
    const float* __restrict__ A, const float* __restrict__ B, float* __restrict__ C,
    const float* __restrict__ bias, const float* __restrict__ res,
    int M, int N, int K, int ldb, int gelu_flag)
{
    __shared__ float As[2][KT][SMS];   // [k][m]
    __shared__ float Bs[2][KT][SMS];   // [k][n]

    const int tid  = threadIdx.x;
    const int lane = tid & 31, warp = tid >> 5;
    const int wm = (warp & 1) * 64;
    const int wn = (warp >> 1) * 32;
    const int crow0 = blockIdx.y * 128, ccol0 = blockIdx.x * 128;

    const int a_r = tid >> 1, a_c = (tid & 1) * 8;
    const int b_r = tid >> 4, b_c = (tid & 15) * 8;

    const float* Ag = A + (size_t)(crow0 + a_r) * K + a_c;
    const float* Bg = B + (size_t)b_r * ldb + ccol0 + b_c;

    float acc[4][4][4];
#pragma unroll
    for (int i = 0; i < 4; i++)
#pragma unroll
        for (int j = 0; j < 4; j++)
#pragma unroll
            for (int k = 0; k < 4; k++) acc[i][j][k] = 0.f;

    const int nk = K / KT;

    {
        float4 av0 = *reinterpret_cast<const float4*>(Ag);
        float4 av1 = *reinterpret_cast<const float4*>(Ag + 4);
        float4 bv0 = *reinterpret_cast<const float4*>(Bg);
        float4 bv1 = *reinterpret_cast<const float4*>(Bg + 4);
        As[0][a_c + 0][a_r] = to_tf32(av0.x);
        As[0][a_c + 1][a_r] = to_tf32(av0.y);
        As[0][a_c + 2][a_r] = to_tf32(av0.z);
        As[0][a_c + 3][a_r] = to_tf32(av0.w);
        As[0][a_c + 4][a_r] = to_tf32(av1.x);
        As[0][a_c + 5][a_r] = to_tf32(av1.y);
        As[0][a_c + 6][a_r] = to_tf32(av1.z);
        As[0][a_c + 7][a_r] = to_tf32(av1.w);
        float4 t0 = make_float4(to_tf32(bv0.x), to_tf32(bv0.y), to_tf32(bv0.z), to_tf32(bv0.w));
        float4 t1 = make_float4(to_tf32(bv1.x), to_tf32(bv1.y), to_tf32(bv1.z), to_tf32(bv1.w));
        *reinterpret_cast<float4*>(&Bs[0][b_r][b_c])     = t0;
        *reinterpret_cast<float4*>(&Bs[0][b_r][b_c + 4]) = t1;
    }
    __syncthreads();

    for (int kt = 0; kt < nk; kt++) {
        const int cur = kt & 1, nxt = cur ^ 1;

        float4 av0, av1, bv0, bv1;
        const bool more = (kt + 1 < nk);
        if (more) {
            const float* Ap = Ag + (kt + 1) * KT;
            const float* Bp = Bg + (size_t)(kt + 1) * KT * ldb;
            av0 = *reinterpret_cast<const float4*>(Ap);
            av1 = *reinterpret_cast<const float4*>(Ap + 4);
            bv0 = *reinterpret_cast<const float4*>(Bp);
            bv1 = *reinterpret_cast<const float4*>(Bp + 4);
        }

#pragma unroll
        for (int kk = 0; kk < KT; kk += 8) {
            uint32_t af[4][4], bf[4][2];
            const int kc = kk + (lane & 3);
#pragma unroll
            for (int am = 0; am < 4; am++) {
                const int r = wm + am * 16 + (lane >> 2);
                af[am][0] = __float_as_uint(As[cur][kc][r]);
                af[am][1] = __float_as_uint(As[cur][kc][r + 8]);
                af[am][2] = __float_as_uint(As[cur][kc + 4][r]);
                af[am][3] = __float_as_uint(As[cur][kc + 4][r + 8]);
            }
#pragma unroll
            for (int bn = 0; bn < 4; bn++) {
                const int cc = wn + bn * 8 + (lane >> 2);
                bf[bn][0] = __float_as_uint(Bs[cur][kc][cc]);
                bf[bn][1] = __float_as_uint(Bs[cur][kc + 4][cc]);
            }
#pragma unroll
            for (int am = 0; am < 4; am++)
#pragma unroll
                for (int bn = 0; bn < 4; bn++)
                    mma_tf32(acc[am][bn], af[am], bf[bn]);
        }

        if (more) {
            As[nxt][a_c + 0][a_r] = to_tf32(av0.x);
            As[nxt][a_c + 1][a_r] = to_tf32(av0.y);
            As[nxt][a_c + 2][a_r] = to_tf32(av0.z);
            As[nxt][a_c + 3][a_r] = to_tf32(av0.w);
            As[nxt][a_c + 4][a_r] = to_tf32(av1.x);
            As[nxt][a_c + 5][a_r] = to_tf32(av1.y);
            As[nxt][a_c + 6][a_r] = to_tf32(av1.z);
            As[nxt][a_c + 7][a_r] = to_tf32(av1.w);
            float4 t0 = make_float4(to_tf32(bv0.x), to_tf32(bv0.y), to_tf32(bv0.z), to_tf32(bv0.w));
            float4 t1 = make_float4(to_tf32(bv1.x), to_tf32(bv1.y), to_tf32(bv1.z), to_tf32(bv1.w));
            *reinterpret_cast<float4*>(&Bs[nxt][b_r][b_c])     = t0;
            *reinterpret_cast<float4*>(&Bs[nxt][b_r][b_c + 4]) = t1;
            __syncthreads();
        }
    }

#pragma unroll
    for (int am = 0; am < 4; am++) {
        const int r0 = crow0 + wm + am * 16 + (lane >> 2);
#pragma unroll
        for (int bn = 0; bn < 4; bn++) {
            const int c0 = ccol0 + wn + bn * 8 + (lane & 3) * 2;
            float v0 = acc[am][bn][0], v1 = acc[am][bn][1];
            float v2 = acc[am][bn][2], v3 = acc[am][bn][3];
            if (bias) {
                float b0 = bias[c0], b1 = bias[c0 + 1];
                v0 += b0; v1 += b1; v2 += b0; v3 += b1;
            }
            if (gelu_flag) {
                v0 = 0.5f * v0 * (1.f + erff(v0 * 0.70710678118654752f));
                v1 = 0.5f * v1 * (1.f + erff(v1 * 0.70710678118654752f));
                v2 = 0.5f * v2 * (1.f + erff(v2 * 0.70710678118654752f));
                v3 = 0.5f * v3 * (1.f + erff(v3 * 0.70710678118654752f));
            }
            size_t i0 = (size_t)r0 * N + c0;
            size_t i1 = (size_t)(r0 + 8) * N + c0;
            if (res) {
                v0 += res[i0]; v1 += res[i0 + 1];
                v2 += res[i1]; v3 += res[i1 + 1];
            }
            *reinterpret_cast<float2*>(C + i0) = make_float2(v0, v1);
            *reinterpret_cast<float2*>(C + i1) = make_float2(v2, v3);
        }
    }
}

// ---------------- small-M GEMM (M<=16), fp32 ----------------
// Grid: N/128 blocks, 512 threads. 4 row-groups of 128 threads; group rg
// computes rows [4rg, 4rg+4) for one column each. A chunked through smem.
#define SG_KC 256
__global__ void __launch_bounds__(512, 2) smallgemm_kernel(
    const float* __restrict__ A, const float* __restrict__ B, float* __restrict__ C,
    const float* __restrict__ bias, const float* __restrict__ res,
    int M, int N, int K, int ldb, int gelu_flag)
{
    __shared__ float As[16][SG_KC];
    const int tid = threadIdx.x;          // 0..511
    const int col = blockIdx.x * 128 + (tid & 127);
    const int rg  = tid >> 7;             // 0..3
    const int r0  = rg * 4;

    float acc[4] = {0.f, 0.f, 0.f, 0.f};

    for (int kc = 0; kc < K; kc += SG_KC) {
        for (int idx = tid; idx < 16 * SG_KC; idx += 512) {
            int r = idx >> 8, k = idx & (SG_KC - 1);
            As[r][k] = (r < M) ? A[(size_t)r * K + kc + k] : 0.f;
        }
        __syncthreads();
#pragma unroll 4
        for (int k = 0; k < SG_KC; k++) {
            float bk = B[(size_t)(kc + k) * ldb + col];
#pragma unroll
            for (int r = 0; r < 4; r++)
                acc[r] = fmaf(As[r0 + r][k], bk, acc[r]);
        }
        __syncthreads();
    }

#pragma unroll
    for (int r = 0; r < 4; r++) {
        int gr = r0 + r;
        if (gr >= M) break;
        float v = acc[r];
        if (bias) v += bias[col];
        if (gelu_flag) v = 0.5f * v * (1.f + erff(v * 0.70710678118654752f));
        size_t idx = (size_t)gr * N + col;
        if (res) v += res[idx];
        C[idx] = v;
    }
}

// ---------------- rotary embedding ----------------
__global__ void rotary_kernel(float* __restrict__ Q, float* __restrict__ K)
{
    int i = blockIdx.x;
    int t = threadIdx.x;
    int h = t >> 5, d = t & 31;
    float inv = 1.f / powf(10000.f, (float)(2 * d) / 64.f);
    float ang = (float)i * inv;
    float s, c;
    sincosf(ang, &s, &c);
    int base = i * DMODEL + h * DHEAD + d;
    float a = Q[base], b2 = Q[base + 32];
    Q[base]      = a * c - b2 * s;
    Q[base + 32] = b2 * c + a * s;
    a = K[base]; b2 = K[base + 32];
    K[base]      = a * c - b2 * s;
    K[base + 32] = b2 * c + a * s;
}

// ---------------- global-token attention ----------------
__global__ void global_attn_kernel(const float* __restrict__ QG,
                                   const float* __restrict__ KVG,
                                   const float* __restrict__ KVX,
                                   float* __restrict__ GO)
{
    __shared__ float q[64];
    __shared__ float lg[129];
    int w = blockIdx.x, h = blockIdx.y;
    int tid = threadIdx.x;
    if (tid < 64) q[tid] = QG[w * DMODEL + h * DHEAD + tid];
    __syncthreads();
    if (tid < 129) {
        const float* kp = (tid == 0)
            ? (KVG + (size_t)w * 1024 + h * DHEAD)
            : (KVX + (size_t)(w * WSZ + tid - 1) * 1024 + h * DHEAD);
        float dt = 0.f;
#pragma unroll
        for (int d = 0; d < 64; d++) dt = fmaf(q[d], kp[d], dt);
        lg[tid] = dt * 0.125f;
    }
    __syncthreads();
    float m = -1e30f;
    for (int j = 0; j < 129; j++) m = fmaxf(m, lg[j]);
    float s = 0.f;
    for (int j = 0; j < 129; j++) s += expf(lg[j] - m);
    if (tid < 64) {
        float acc = 0.f;
        for (int j = 0; j < 129; j++) {
            float p = expf(lg[j] - m);
            float v = (j == 0)
                ? KVG[(size_t)w * 1024 + 512 + h * DHEAD + tid]
                : KVX[(size_t)(w * WSZ + j - 1) * 1024 + 512 + h * DHEAD + tid];
            acc = fmaf(p, v, acc);
        }
        GO[w * DMODEL + h * DHEAD + tid] = acc / s;
    }
}

// ---------------- local windowed attention ----------------
__global__ void local_attn_kernel(const float* __restrict__ Q,
                                  const float* __restrict__ K,
                                  const float* __restrict__ GKV,
                                  float* __restrict__ AO)
{
    extern __shared__ float sm[];
    float* sk  = sm;                 // [271][64]
    float* sgv = sm + 271 * 64;      // [15][64]
    int w = blockIdx.x, h = blockIdx.y;
    int tid = threadIdx.x;           // 128

    for (int idx = tid; idx < 15 * 64; idx += 128) {
        int j = idx >> 6, d = idx & 63;
        sk[idx]  = GKV[(size_t)j * 1024 + h * DHEAD + d];
        sgv[idx] = GKV[(size_t)j * 1024 + 512 + h * DHEAD + d];
    }
    for (int idx = tid; idx < 256 * 64; idx += 128) {
        int c = idx >> 6, d = idx & 63;
        int t = (w - 1) * WSZ + c;
        sk[15 * 64 + idx] = (t >= 0) ? K[(size_t)t * DMODEL + h * DHEAD + d] : 0.f;
    }
    __syncthreads();

    const int i = tid;
    float q[64];
    const float* qp = Q + (size_t)(w * WSZ + i) * DMODEL + h * DHEAD;
#pragma unroll
    for (int d = 0; d < 64; d++) q[d] = qp[d];

    const int jend = 15 + i + 128;

    float m = -1e30f;
    for (int j = 0; j < w; j++) {
        const float* kp = sk + j * 64;
        float dt = 0.f;
#pragma unroll
        for (int d = 0; d < 64; d++) dt = fmaf(q[d], kp[d], dt);
        m = fmaxf(m, dt * 0.125f);
    }
    for (int j = 15; j <= jend; j++) {
        const float* kp = sk + j * 64;
        float dt = 0.f;
#pragma unroll
        for (int d = 0; d < 64; d++) dt = fmaf(q[d], kp[d], dt);
        m = fmaxf(m, dt * 0.125f);
    }

    float s = 0.f;
    float acc[64];
#pragma unroll
    for (int d = 0; d < 64; d++) acc[d] = 0.f;
    for (int j = 0; j < w; j++) {
        const float* kp = sk + j * 64;
        float dt = 0.f;
#pragma unroll
        for (int d = 0; d < 64; d++) dt = fmaf(q[d], kp[d], dt);
        float e = expf(dt * 0.125f - m);
        s += e;
        const float* vp = sgv + j * 64;
#pragma unroll
        for (int d = 0; d < 64; d++) acc[d] = fmaf(e, vp[d], acc[d]);
    }
    for (int j = 15; j <= jend; j++) {
        const float* kp = sk + j * 64;
        float dt = 0.f;
#pragma unroll
        for (int d = 0; d < 64; d++) dt = fmaf(q[d], kp[d], dt);
        float e = expf(dt * 0.125f - m);
        s += e;
#pragma unroll
        for (int d = 0; d < 64; d++) acc[d] = fmaf(e, kp[d], acc[d]);
    }
    float inv = 1.f / s;
    float* op = AO + (size_t)(w * WSZ + i) * DMODEL + h * DHEAD;
#pragma unroll
    for (int d = 0; d < 64; d++) op[d] = acc[d] * inv;
}

// ---------------- host orchestration ----------------
static inline dim3 gg(int M, int N) { return dim3(N / 128, (M + 127) / 128); }

extern "C" void kernel_launch(void* const* d_in, const int* in_sizes, int n_in,
                              void* d_out, int out_size)
{
    const int*   tokens     = (const int*)  d_in[0];
    const float* tok_emb    = (const float*)d_in[1];
    const float* gpos_emb   = (const float*)d_in[2];
    const float* g_norm_w   = (const float*)d_in[3];
    const float* g_norm_b   = (const float*)d_in[4];
    const float* g_Wq       = (const float*)d_in[5];
    const float* g_Wkv      = (const float*)d_in[6];
    const float* g_Wo       = (const float*)d_in[7];
    const float* g_bo       = (const float*)d_in[8];
    const float* gff_norm_w = (const float*)d_in[9];
    const float* gff_norm_b = (const float*)d_in[10];
    const float* gff_W1     = (const float*)d_in[11];
    const float* gff_b1     = (const float*)d_in[12];
    const float* gff_W2     = (const float*)d_in[13];
    const float* gff_b2     = (const float*)d_in[14];
    const float* la_norm_w  = (const float*)d_in[15];
    const float* la_norm_b  = (const float*)d_in[16];
    const float* la_Wq      = (const float*)d_in[17];
    const float* la_Wkv     = (const float*)d_in[18];
    const float* la_Wo      = (const float*)d_in[19];
    const float* la_bo      = (const float*)d_in[20];
    const float* lff_norm_w = (const float*)d_in[21];
    const float* lff_norm_b = (const float*)d_in[22];
    const float* lff_W1     = (const float*)d_in[23];
    const float* lff_b1     = (const float*)d_in[24];
    const float* lff_W2     = (const float*)d_in[25];
    const float* lff_b2     = (const float*)d_in[26];
    const float* out_norm_w = (const float*)d_in[27];
    const float* out_norm_b = (const float*)d_in[28];
    const float* out_W      = (const float*)d_in[29];
    const float* out_b      = (const float*)d_in[30];

    float *X, *XN, *Q, *K, *KVX, *H, *AO, *G, *GN, *QG, *KVG, *GO, *GH, *GKV;
    cudaGetSymbolAddress((void**)&X,   g_X);
    cudaGetSymbolAddress((void**)&XN,  g_XN);
    cudaGetSymbolAddress((void**)&Q,   g_Q);
    cudaGetSymbolAddress((void**)&K,   g_K);
    cudaGetSymbolAddress((void**)&KVX, g_KVX);
    cudaGetSymbolAddress((void**)&H,   g_H);
    cudaGetSymbolAddress((void**)&AO,  g_AO);
    cudaGetSymbolAddress((void**)&G,   g_G);
    cudaGetSymbolAddress((void**)&GN,  g_GN);
    cudaGetSymbolAddress((void**)&QG,  g_QG);
    cudaGetSymbolAddress((void**)&KVG, g_KVG);
    cudaGetSymbolAddress((void**)&GO,  g_GO);
    cudaGetSymbolAddress((void**)&GH,  g_GH);
    cudaGetSymbolAddress((void**)&GKV, g_GKV);

    cudaFuncSetAttribute(local_attn_kernel,
                         cudaFuncAttributeMaxDynamicSharedMemorySize, 73216);

    embed_kernel<<<NTOK, DMODEL>>>(tokens, tok_emb, X);
    winmean_kernel<<<NWIN, DMODEL>>>(X, gpos_emb, G);

    for (int l = 0; l < 2; l++) {
        // ---- global-token transformer (shared weights) ----
        ln_kernel<<<NWIN, 256>>>(G, GN, g_norm_w, g_norm_b);
        smallgemm_kernel<<<4,  512>>>(GN, g_Wq,  QG,  nullptr, nullptr, 16, 512,  512, 512,  0);
        smallgemm_kernel<<<8,  512>>>(GN, g_Wkv, KVG, nullptr, nullptr, 16, 1024, 512, 1024, 0);
        tf32gemm_kernel<<<gg(2048, 1024), 256>>>(X, g_Wkv, KVX, nullptr, nullptr, 2048, 1024, 512, 1024, 0);
        global_attn_kernel<<<dim3(16, 8), 256>>>(QG, KVG, KVX, GO);
        smallgemm_kernel<<<4,  512>>>(GO, g_Wo, G, g_bo, G, 16, 512, 512, 512, 0);
        ln_kernel<<<NWIN, 256>>>(G, GN, gff_norm_w, gff_norm_b);
        smallgemm_kernel<<<16, 512>>>(GN, gff_W1, GH, gff_b1, nullptr, 16, 2048, 512,  2048, 1);
        smallgemm_kernel<<<4,  512>>>(GH, gff_W2, G,  gff_b2, G,       16, 512,  2048, 512,  0);

        // ---- local windowed attention ----
        ln_kernel<<<NTOK, 256>>>(X, XN, la_norm_w + l * 512, la_norm_b + l * 512);
        tf32gemm_kernel<<<gg(2048, 512), 256>>>(XN, la_Wq  + (size_t)l * 512 * 512,  Q, nullptr, nullptr, 2048, 512, 512, 512,  0);
        tf32gemm_kernel<<<gg(2048, 512), 256>>>(XN, la_Wkv + (size_t)l * 512 * 1024, K, nullptr, nullptr, 2048, 512, 512, 1024, 0);
        smallgemm_kernel<<<8, 512>>>(G, la_Wkv + (size_t)l * 512 * 1024, GKV, nullptr, nullptr, 15, 1024, 512, 1024, 0);
        rotary_kernel<<<NTOK, 256>>>(Q, K);
        local_attn_kernel<<<dim3(16, 8), 128, 73216>>>(Q, K, GKV, AO);
        tf32gemm_kernel<<<gg(2048, 512), 256>>>(AO, la_Wo + (size_t)l * 512 * 512, X, la_bo + l * 512, X, 2048, 512, 512, 512, 0);

        // ---- local FF ----
        ln_kernel<<<NTOK, 256>>>(X, XN, lff_norm_w + l * 512, lff_norm_b + l * 512);
        tf32gemm_kernel<<<gg(2048, 2048), 256>>>(XN, lff_W1 + (size_t)l * 512 * 2048, H, lff_b1 + l * 2048, nullptr, 2048, 2048, 512,  2048, 1);
        tf32gemm_kernel<<<gg(2048, 512),  256>>>(H,  lff_W2 + (size_t)l * 2048 * 512, X, lff_b2 + l * 512,  X,       2048, 512,  2048, 512,  0);
    }

    // ---- output head ----
    ln_kernel<<<NTOK, 256>>>(X, XN, out_norm_w, out_norm_b);
    tf32gemm_kernel<<<gg(2048, 32000), 256>>>(XN, out_W, (float*)d_out, out_b, nullptr,
                                              2048, 32000, 512, 32000, 0);
}

// round 4
// speedup vs baseline: 2.5814x; 1.2443x over previous
#include <cuda_runtime.h>
#include <math.h>
#include <stdint.h>

// ---------------- model constants ----------------
#define DMODEL 512
#define NTOK   2048
#define NWIN   16
#define WSZ    128
#define NHEAD  8
#define DHEAD  64
#define FFDIM  2048

// ---------------- scratch (no allocs allowed) ----------------
__device__ alignas(128) float g_X  [NTOK * DMODEL];
__device__ alignas(128) float g_XN [NTOK * DMODEL];
__device__ alignas(128) float g_Q  [NTOK * DMODEL];
__device__ alignas(128) float g_K  [NTOK * DMODEL];
__device__ alignas(128) float g_KVX[NTOK * 2 * DMODEL];
__device__ alignas(128) float g_H  [NTOK * FFDIM];
__device__ alignas(128) float g_AO [NTOK * DMODEL];
__device__ alignas(128) float g_G  [NWIN * DMODEL];
__device__ alignas(128) float g_GN [NWIN * DMODEL];
__device__ alignas(128) float g_QG [NWIN * DMODEL];
__device__ alignas(128) float g_KVG[NWIN * 2 * DMODEL];
__device__ alignas(128) float g_GO [NWIN * DMODEL];
__device__ alignas(128) float g_GH [NWIN * FFDIM];
__device__ alignas(128) float g_GKV[NWIN * 2 * DMODEL];

// ---------------- embedding gather ----------------
__global__ void embed_kernel(const int* __restrict__ tokens,
                             const float* __restrict__ emb,
                             float* __restrict__ X)
{
    int row = blockIdx.x;
    int d   = threadIdx.x;
    X[row * DMODEL + d] = emb[(size_t)tokens[row] * DMODEL + d];
}

// ---------------- window mean + pos emb ----------------
__global__ void winmean_kernel(const float* __restrict__ X,
                               const float* __restrict__ gpos,
                               float* __restrict__ G)
{
    int w = blockIdx.x;
    int d = threadIdx.x;
    float s = 0.f;
    for (int i = 0; i < WSZ; i++)
        s += X[(w * WSZ + i) * DMODEL + d];
    G[w * DMODEL + d] = s * (1.f / 128.f) + gpos[w * DMODEL + d];
}

// ---------------- layernorm ----------------
__global__ void ln_kernel(const float* __restrict__ in, float* __restrict__ out,
                          const float* __restrict__ w, const float* __restrict__ b)
{
    __shared__ float sh[8];
    __shared__ float stat;
    int row = blockIdx.x;
    int tid = threadIdx.x;
    const float* r = in + (size_t)row * DMODEL;
    float x0 = r[tid], x1 = r[tid + 256];

    float v = x0 + x1;
    for (int o = 16; o; o >>= 1) v += __shfl_down_sync(0xffffffffu, v, o);
    if ((tid & 31) == 0) sh[tid >> 5] = v;
    __syncthreads();
    if (tid == 0) {
        float t = 0.f;
        for (int i = 0; i < 8; i++) t += sh[i];
        stat = t * (1.f / 512.f);
    }
    __syncthreads();
    float mu = stat;
    float d0 = x0 - mu, d1 = x1 - mu;
    __syncthreads();
    v = d0 * d0 + d1 * d1;
    for (int o = 16; o; o >>= 1) v += __shfl_down_sync(0xffffffffu, v, o);
    if ((tid & 31) == 0) sh[tid >> 5] = v;
    __syncthreads();
    if (tid == 0) {
        float t = 0.f;
        for (int i = 0; i < 8; i++) t += sh[i];
        stat = t * (1.f / 512.f);
    }
    __syncthreads();
    float rstd = rsqrtf(stat + 1e-5f);
    out[(size_t)row * DMODEL + tid]       = d0 * rstd * w[tid]       + b[tid];
    out[(size_t)row * DMODEL + tid + 256] = d1 * rstd * w[tid + 256] + b[tid + 256];
}

// ---------------- tf32 helpers ----------------
__device__ __forceinline__ float to_tf32(float x)
{
    float r;
    asm("cvt.rna.tf32.f32 %0, %1;" : "=f"(r) : "f"(x));
    return r;
}

__device__ __forceinline__ void mma_tf32(float* c, const uint32_t* a, const uint32_t* b)
{
    asm volatile(
        "mma.sync.aligned.m16n8k8.row.col.f32.tf32.tf32.f32 "
        "{%0,%1,%2,%3}, {%4,%5,%6,%7}, {%8,%9}, {%0,%1,%2,%3};"
        : "+f"(c[0]), "+f"(c[1]), "+f"(c[2]), "+f"(c[3])
        : "r"(a[0]), "r"(a[1]), "r"(a[2]), "r"(a[3]), "r"(b[0]), "r"(b[1]));
}

// ---------------- tf32 tensor-core GEMM (M%128==0, N%128==0, K%16==0) ----------------
// A-smem: XOR-swizzled pair-interleaved layout Asw[buf][g][r][8]:
//   within k-group g (8 k's), value (k'=c+4*hi, row r) lives at slot 2*(c^(r&3))+hi.
//   Fragment (kc, kc+4) for row r = one float2 at slot 2*((lane&3)^(r&3)).
//   Row stride 8 floats (8 mod 32) + XOR -> conflict-free LDS.64 in both phases.
#define KT 16
#define SMS 136
__global__ void __launch_bounds__(256, 2) tf32gemm_kernel(
    const float* __restrict__ A, const float* __restrict__ B, float* __restrict__ C,
    const float* __restrict__ bias, const float* __restrict__ res,
    int M, int N, int K, int ldb, int gelu_flag)
{
    __shared__ float Asw[2][2][128][8];   // [buf][g][row][slot]
    __shared__ float Bs[2][KT][SMS];      // [buf][k][n]

    const int tid  = threadIdx.x;
    const int lane = tid & 31, warp = tid >> 5;
    const int wm = (warp & 1) * 64;
    const int wn = (warp >> 1) * 32;
    const int crow0 = blockIdx.y * 128, ccol0 = blockIdx.x * 128;

    const int a_r = tid >> 1, a_g = tid & 1;          // A: row, k-group
    const int a_r3 = a_r & 3;
    const int b_r = tid >> 4, b_c = (tid & 15) * 8;   // B: k, col

    const float* Ag = A + (size_t)(crow0 + a_r) * K + a_g * 8;
    const float* Bg = B + (size_t)b_r * ldb + ccol0 + b_c;

    const int r3q = (lane >> 2) & 3;
    const int so  = 2 * ((lane & 3) ^ r3q);           // fragment slot offset

    float acc[4][4][4];
#pragma unroll
    for (int i = 0; i < 4; i++)
#pragma unroll
        for (int j = 0; j < 4; j++)
#pragma unroll
            for (int k = 0; k < 4; k++) acc[i][j][k] = 0.f;

    const int nk = K / KT;

    // ---- stage tile 0 ----
    {
        float4 av0 = *reinterpret_cast<const float4*>(Ag);
        float4 av1 = *reinterpret_cast<const float4*>(Ag + 4);
        float av[8] = {av0.x, av0.y, av0.z, av0.w, av1.x, av1.y, av1.z, av1.w};
        float sv[8];
#pragma unroll
        for (int cp = 0; cp < 4; cp++) {
            sv[2 * cp]     = to_tf32(av[cp ^ a_r3]);
            sv[2 * cp + 1] = to_tf32(av[(cp ^ a_r3) + 4]);
        }
        *reinterpret_cast<float4*>(&Asw[0][a_g][a_r][0]) = make_float4(sv[0], sv[1], sv[2], sv[3]);
        *reinterpret_cast<float4*>(&Asw[0][a_g][a_r][4]) = make_float4(sv[4], sv[5], sv[6], sv[7]);

        float4 bv0 = *reinterpret_cast<const float4*>(Bg);
        float4 bv1 = *reinterpret_cast<const float4*>(Bg + 4);
        float4 t0 = make_float4(to_tf32(bv0.x), to_tf32(bv0.y), to_tf32(bv0.z), to_tf32(bv0.w));
        float4 t1 = make_float4(to_tf32(bv1.x), to_tf32(bv1.y), to_tf32(bv1.z), to_tf32(bv1.w));
        *reinterpret_cast<float4*>(&Bs[0][b_r][b_c])     = t0;
        *reinterpret_cast<float4*>(&Bs[0][b_r][b_c + 4]) = t1;
    }
    __syncthreads();

    for (int kt = 0; kt < nk; kt++) {
        const int cur = kt & 1, nxt = cur ^ 1;

        float4 av0, av1, bv0, bv1;
        const bool more = (kt + 1 < nk);
        if (more) {
            const float* Ap = Ag + (kt + 1) * KT;
            const float* Bp = Bg + (size_t)(kt + 1) * KT * ldb;
            av0 = *reinterpret_cast<const float4*>(Ap);
            av1 = *reinterpret_cast<const float4*>(Ap + 4);
            bv0 = *reinterpret_cast<const float4*>(Bp);
            bv1 = *reinterpret_cast<const float4*>(Bp + 4);
        }

#pragma unroll
        for (int kk = 0; kk < KT; kk += 8) {
            const int g = kk >> 3;
            uint32_t af[4][4], bf[4][2];
            const int kc = kk + (lane & 3);
#pragma unroll
            for (int am = 0; am < 4; am++) {
                const int r = wm + am * 16 + (lane >> 2);
                float2 p0 = *reinterpret_cast<const float2*>(&Asw[cur][g][r][so]);
                float2 p1 = *reinterpret_cast<const float2*>(&Asw[cur][g][r + 8][so]);
                af[am][0] = __float_as_uint(p0.x);
                af[am][1] = __float_as_uint(p1.x);
                af[am][2] = __float_as_uint(p0.y);
                af[am][3] = __float_as_uint(p1.y);
            }
#pragma unroll
            for (int bn = 0; bn < 4; bn++) {
                const int cc = wn + bn * 8 + (lane >> 2);
                bf[bn][0] = __float_as_uint(Bs[cur][kc][cc]);
                bf[bn][1] = __float_as_uint(Bs[cur][kc + 4][cc]);
            }
#pragma unroll
            for (int am = 0; am < 4; am++)
#pragma unroll
                for (int bn = 0; bn < 4; bn++)
                    mma_tf32(acc[am][bn], af[am], bf[bn]);
        }

        if (more) {
            float av[8] = {av0.x, av0.y, av0.z, av0.w, av1.x, av1.y, av1.z, av1.w};
            float sv[8];
#pragma unroll
            for (int cp = 0; cp < 4; cp++) {
                sv[2 * cp]     = to_tf32(av[cp ^ a_r3]);
                sv[2 * cp + 1] = to_tf32(av[(cp ^ a_r3) + 4]);
            }
            *reinterpret_cast<float4*>(&Asw[nxt][a_g][a_r][0]) = make_float4(sv[0], sv[1], sv[2], sv[3]);
            *reinterpret_cast<float4*>(&Asw[nxt][a_g][a_r][4]) = make_float4(sv[4], sv[5], sv[6], sv[7]);
            float4 t0 = make_float4(to_tf32(bv0.x), to_tf32(bv0.y), to_tf32(bv0.z), to_tf32(bv0.w));
            float4 t1 = make_float4(to_tf32(bv1.x), to_tf32(bv1.y), to_tf32(bv1.z), to_tf32(bv1.w));
            *reinterpret_cast<float4*>(&Bs[nxt][b_r][b_c])     = t0;
            *reinterpret_cast<float4*>(&Bs[nxt][b_r][b_c + 4]) = t1;
            __syncthreads();
        }
    }

    // ---- epilogue ----
#pragma unroll
    for (int am = 0; am < 4; am++) {
        const int r0 = crow0 + wm + am * 16 + (lane >> 2);
#pragma unroll
        for (int bn = 0; bn < 4; bn++) {
            const int c0 = ccol0 + wn + bn * 8 + (lane & 3) * 2;
            float v0 = acc[am][bn][0], v1 = acc[am][bn][1];
            float v2 = acc[am][bn][2], v3 = acc[am][bn][3];
            if (bias) {
                float b0 = bias[c0], b1 = bias[c0 + 1];
                v0 += b0; v1 += b1; v2 += b0; v3 += b1;
            }
            if (gelu_flag) {
                v0 = 0.5f * v0 * (1.f + erff(v0 * 0.70710678118654752f));
                v1 = 0.5f * v1 * (1.f + erff(v1 * 0.70710678118654752f));
                v2 = 0.5f * v2 * (1.f + erff(v2 * 0.70710678118654752f));
                v3 = 0.5f * v3 * (1.f + erff(v3 * 0.70710678118654752f));
            }
            size_t i0 = (size_t)r0 * N + c0;
            size_t i1 = (size_t)(r0 + 8) * N + c0;
            if (res) {
                v0 += res[i0]; v1 += res[i0 + 1];
                v2 += res[i1]; v3 += res[i1 + 1];
            }
            *reinterpret_cast<float2*>(C + i0) = make_float2(v0, v1);
            *reinterpret_cast<float2*>(C + i1) = make_float2(v2, v3);
        }
    }
}

// ---------------- small-M GEMM (M<=16), fp32, split-K within block ----------------
// 1024 threads: (tid&127)=col, grp=tid>>7: half=grp>>2 (K-half), rg=grp&3 (4 rows).
// A chunks staged in smem for both halves; B loads batched 16-wide for MLP.
// Halves combined through smem in fixed order (deterministic).
#define SG_KC 256
__global__ void __launch_bounds__(1024, 1) smallgemm_kernel(
    const float* __restrict__ A, const float* __restrict__ B, float* __restrict__ C,
    const float* __restrict__ bias, const float* __restrict__ res,
    int M, int N, int K, int ldb, int gelu_flag)
{
    __shared__ float As[2][16][SG_KC];   // [half][row][k]
    __shared__ float Ps[16][128];        // upper-half partials
    const int tid  = threadIdx.x;
    const int col  = blockIdx.x * 128 + (tid & 127);
    const int grp  = tid >> 7;           // 0..7
    const int half = grp >> 2;           // 0,1
    const int rg   = grp & 3;            // row group
    const int Kh   = K >> 1;

    float acc[4] = {0.f, 0.f, 0.f, 0.f};
    const float* Bp = B + (size_t)half * Kh * ldb + col;

    for (int kc = 0; kc < Kh; kc += SG_KC) {
        for (int idx = tid; idx < 2 * 16 * SG_KC; idx += 1024) {
            int h = idx >> 12;
            int r = (idx >> 8) & 15;
            int k = idx & (SG_KC - 1);
            As[h][r][k] = (r < M) ? A[(size_t)r * K + h * Kh + kc + k] : 0.f;
        }
        __syncthreads();
#pragma unroll 1
        for (int k0 = 0; k0 < SG_KC; k0 += 16) {
            float bv[16];
#pragma unroll
            for (int u = 0; u < 16; u++)
                bv[u] = Bp[(size_t)(kc + k0 + u) * ldb];
#pragma unroll
            for (int u = 0; u < 16; u++) {
#pragma unroll
                for (int r = 0; r < 4; r++)
                    acc[r] = fmaf(As[half][rg * 4 + r][k0 + u], bv[u], acc[r]);
            }
        }
        __syncthreads();
    }

    if (half == 1) {
#pragma unroll
        for (int r = 0; r < 4; r++)
            Ps[rg * 4 + r][tid & 127] = acc[r];
    }
    __syncthreads();
    if (half == 0) {
#pragma unroll
        for (int r = 0; r < 4; r++) {
            int gr = rg * 4 + r;
            if (gr >= M) continue;
            float v = acc[r] + Ps[gr][tid & 127];
            if (bias) v += bias[col];
            if (gelu_flag) v = 0.5f * v * (1.f + erff(v * 0.70710678118654752f));
            size_t idx = (size_t)gr * N + col;
            if (res) v += res[idx];
            C[idx] = v;
        }
    }
}

// ---------------- rotary embedding ----------------
__global__ void rotary_kernel(float* __restrict__ Q, float* __restrict__ K)
{
    int i = blockIdx.x;
    int t = threadIdx.x;
    int h = t >> 5, d = t & 31;
    float inv = 1.f / powf(10000.f, (float)(2 * d) / 64.f);
    float ang = (float)i * inv;
    float s, c;
    sincosf(ang, &s, &c);
    int base = i * DMODEL + h * DHEAD + d;
    float a = Q[base], b2 = Q[base + 32];
    Q[base]      = a * c - b2 * s;
    Q[base + 32] = b2 * c + a * s;
    a = K[base]; b2 = K[base + 32];
    K[base]      = a * c - b2 * s;
    K[base + 32] = b2 * c + a * s;
}

// ---------------- global-token attention ----------------
__global__ void global_attn_kernel(const float* __restrict__ QG,
                                   const float* __restrict__ KVG,
                                   const float* __restrict__ KVX,
                                   float* __restrict__ GO)
{
    __shared__ float q[64];
    __shared__ float lg[129];
    int w = blockIdx.x, h = blockIdx.y;
    int tid = threadIdx.x;
    if (tid < 64) q[tid] = QG[w * DMODEL + h * DHEAD + tid];
    __syncthreads();
    if (tid < 129) {
        const float* kp = (tid == 0)
            ? (KVG + (size_t)w * 1024 + h * DHEAD)
            : (KVX + (size_t)(w * WSZ + tid - 1) * 1024 + h * DHEAD);
        float dt = 0.f;
#pragma unroll
        for (int d = 0; d < 64; d++) dt = fmaf(q[d], kp[d], dt);
        lg[tid] = dt * 0.125f;
    }
    __syncthreads();
    float m = -1e30f;
    for (int j = 0; j < 129; j++) m = fmaxf(m, lg[j]);
    float s = 0.f;
    for (int j = 0; j < 129; j++) s += expf(lg[j] - m);
    if (tid < 64) {
        float acc = 0.f;
        for (int j = 0; j < 129; j++) {
            float p = expf(lg[j] - m);
            float v = (j == 0)
                ? KVG[(size_t)w * 1024 + 512 + h * DHEAD + tid]
                : KVX[(size_t)(w * WSZ + j - 1) * 1024 + 512 + h * DHEAD + tid];
            acc = fmaf(p, v, acc);
        }
        GO[w * DMODEL + h * DHEAD + tid] = acc / s;
    }
}

// ---------------- local windowed attention ----------------
__global__ void local_attn_kernel(const float* __restrict__ Q,
                                  const float* __restrict__ K,
                                  const float* __restrict__ GKV,
                                  float* __restrict__ AO)
{
    extern __shared__ float sm[];
    float* sk  = sm;                 // [271][64]
    float* sgv = sm + 271 * 64;      // [15][64]
    int w = blockIdx.x, h = blockIdx.y;
    int tid = threadIdx.x;           // 128

    for (int idx = tid; idx < 15 * 64; idx += 128) {
        int j = idx >> 6, d = idx & 63;
        sk[idx]  = GKV[(size_t)j * 1024 + h * DHEAD + d];
        sgv[idx] = GKV[(size_t)j * 1024 + 512 + h * DHEAD + d];
    }
    for (int idx = tid; idx < 256 * 64; idx += 128) {
        int c = idx >> 6, d = idx & 63;
        int t = (w - 1) * WSZ + c;
        sk[15 * 64 + idx] = (t >= 0) ? K[(size_t)t * DMODEL + h * DHEAD + d] : 0.f;
    }
    __syncthreads();

    const int i = tid;
    float q[64];
    const float* qp = Q + (size_t)(w * WSZ + i) * DMODEL + h * DHEAD;
#pragma unroll
    for (int d = 0; d < 64; d++) q[d] = qp[d];

    const int jend = 15 + i + 128;

    float m = -1e30f;
    for (int j = 0; j < w; j++) {
        const float* kp = sk + j * 64;
        float dt = 0.f;
#pragma unroll
        for (int d = 0; d < 64; d++) dt = fmaf(q[d], kp[d], dt);
        m = fmaxf(m, dt * 0.125f);
    }
    for (int j = 15; j <= jend; j++) {
        const float* kp = sk + j * 64;
        float dt = 0.f;
#pragma unroll
        for (int d = 0; d < 64; d++) dt = fmaf(q[d], kp[d], dt);
        m = fmaxf(m, dt * 0.125f);
    }

    float s = 0.f;
    float acc[64];
#pragma unroll
    for (int d = 0; d < 64; d++) acc[d] = 0.f;
    for (int j = 0; j < w; j++) {
        const float* kp = sk + j * 64;
        float dt = 0.f;
#pragma unroll
        for (int d = 0; d < 64; d++) dt = fmaf(q[d], kp[d], dt);
        float e = expf(dt * 0.125f - m);
        s += e;
        const float* vp = sgv + j * 64;
#pragma unroll
        for (int d = 0; d < 64; d++) acc[d] = fmaf(e, vp[d], acc[d]);
    }
    for (int j = 15; j <= jend; j++) {
        const float* kp = sk + j * 64;
        float dt = 0.f;
#pragma unroll
        for (int d = 0; d < 64; d++) dt = fmaf(q[d], kp[d], dt);
        float e = expf(dt * 0.125f - m);
        s += e;
#pragma unroll
        for (int d = 0; d < 64; d++) acc[d] = fmaf(e, kp[d], acc[d]);
    }
    float inv = 1.f / s;
    float* op = AO + (size_t)(w * WSZ + i) * DMODEL + h * DHEAD;
#pragma unroll
    for (int d = 0; d < 64; d++) op[d] = acc[d] * inv;
}

// ---------------- host orchestration ----------------
static inline dim3 gg(int M, int N) { return dim3(N / 128, (M + 127) / 128); }

extern "C" void kernel_launch(void* const* d_in, const int* in_sizes, int n_in,
                              void* d_out, int out_size)
{
    const int*   tokens     = (const int*)  d_in[0];
    const float* tok_emb    = (const float*)d_in[1];
    const float* gpos_emb   = (const float*)d_in[2];
    const float* g_norm_w   = (const float*)d_in[3];
    const float* g_norm_b   = (const float*)d_in[4];
    const float* g_Wq       = (const float*)d_in[5];
    const float* g_Wkv      = (const float*)d_in[6];
    const float* g_Wo       = (const float*)d_in[7];
    const float* g_bo       = (const float*)d_in[8];
    const float* gff_norm_w = (const float*)d_in[9];
    const float* gff_norm_b = (const float*)d_in[10];
    const float* gff_W1     = (const float*)d_in[11];
    const float* gff_b1     = (const float*)d_in[12];
    const float* gff_W2     = (const float*)d_in[13];
    const float* gff_b2     = (const float*)d_in[14];
    const float* la_norm_w  = (const float*)d_in[15];
    const float* la_norm_b  = (const float*)d_in[16];
    const float* la_Wq      = (const float*)d_in[17];
    const float* la_Wkv     = (const float*)d_in[18];
    const float* la_Wo      = (const float*)d_in[19];
    const float* la_bo      = (const float*)d_in[20];
    const float* lff_norm_w = (const float*)d_in[21];
    const float* lff_norm_b = (const float*)d_in[22];
    const float* lff_W1     = (const float*)d_in[23];
    const float* lff_b1     = (const float*)d_in[24];
    const float* lff_W2     = (const float*)d_in[25];
    const float* lff_b2     = (const float*)d_in[26];
    const float* out_norm_w = (const float*)d_in[27];
    const float* out_norm_b = (const float*)d_in[28];
    const float* out_W      = (const float*)d_in[29];
    const float* out_b      = (const float*)d_in[30];

    float *X, *XN, *Q, *K, *KVX, *H, *AO, *G, *GN, *QG, *KVG, *GO, *GH, *GKV;
    cudaGetSymbolAddress((void**)&X,   g_X);
    cudaGetSymbolAddress((void**)&XN,  g_XN);
    cudaGetSymbolAddress((void**)&Q,   g_Q);
    cudaGetSymbolAddress((void**)&K,   g_K);
    cudaGetSymbolAddress((void**)&KVX, g_KVX);
    cudaGetSymbolAddress((void**)&H,   g_H);
    cudaGetSymbolAddress((void**)&AO,  g_AO);
    cudaGetSymbolAddress((void**)&G,   g_G);
    cudaGetSymbolAddress((void**)&GN,  g_GN);
    cudaGetSymbolAddress((void**)&QG,  g_QG);
    cudaGetSymbolAddress((void**)&KVG, g_KVG);
    cudaGetSymbolAddress((void**)&GO,  g_GO);
    cudaGetSymbolAddress((void**)&GH,  g_GH);
    cudaGetSymbolAddress((void**)&GKV, g_GKV);

    cudaFuncSetAttribute(local_attn_kernel,
                         cudaFuncAttributeMaxDynamicSharedMemorySize, 73216);

    embed_kernel<<<NTOK, DMODEL>>>(tokens, tok_emb, X);
    winmean_kernel<<<NWIN, DMODEL>>>(X, gpos_emb, G);

    for (int l = 0; l < 2; l++) {
        // ---- global-token transformer (shared weights) ----
        ln_kernel<<<NWIN, 256>>>(G, GN, g_norm_w, g_norm_b);
        // KVX depends only on X — launched early (also lands in ncu's capture slot)
        tf32gemm_kernel<<<gg(2048, 1024), 256>>>(X, g_Wkv, KVX, nullptr, nullptr, 2048, 1024, 512, 1024, 0);
        smallgemm_kernel<<<4,  1024>>>(GN, g_Wq,  QG,  nullptr, nullptr, 16, 512,  512, 512,  0);
        smallgemm_kernel<<<8,  1024>>>(GN, g_Wkv, KVG, nullptr, nullptr, 16, 1024, 512, 1024, 0);
        global_attn_kernel<<<dim3(16, 8), 256>>>(QG, KVG, KVX, GO);
        smallgemm_kernel<<<4,  1024>>>(GO, g_Wo, G, g_bo, G, 16, 512, 512, 512, 0);
        ln_kernel<<<NWIN, 256>>>(G, GN, gff_norm_w, gff_norm_b);
        smallgemm_kernel<<<16, 1024>>>(GN, gff_W1, GH, gff_b1, nullptr, 16, 2048, 512,  2048, 1);
        smallgemm_kernel<<<4,  1024>>>(GH, gff_W2, G,  gff_b2, G,       16, 512,  2048, 512,  0);

        // ---- local windowed attention ----
        ln_kernel<<<NTOK, 256>>>(X, XN, la_norm_w + l * 512, la_norm_b + l * 512);
        tf32gemm_kernel<<<gg(2048, 512), 256>>>(XN, la_Wq  + (size_t)l * 512 * 512,  Q, nullptr, nullptr, 2048, 512, 512, 512,  0);
        tf32gemm_kernel<<<gg(2048, 512), 256>>>(XN, la_Wkv + (size_t)l * 512 * 1024, K, nullptr, nullptr, 2048, 512, 512, 1024, 0);
        smallgemm_kernel<<<8, 1024>>>(G, la_Wkv + (size_t)l * 512 * 1024, GKV, nullptr, nullptr, 15, 1024, 512, 1024, 0);
        rotary_kernel<<<NTOK, 256>>>(Q, K);
        local_attn_kernel<<<dim3(16, 8), 128, 73216>>>(Q, K, GKV, AO);
        tf32gemm_kernel<<<gg(2048, 512), 256>>>(AO, la_Wo + (size_t)l * 512 * 512, X, la_bo + l * 512, X, 2048, 512, 512, 512, 0);

        // ---- local FF ----
        ln_kernel<<<NTOK, 256>>>(X, XN, lff_norm_w + l * 512, lff_norm_b + l * 512);
        tf32gemm_kernel<<<gg(2048, 2048), 256>>>(XN, lff_W1 + (size_t)l * 512 * 2048, H, lff_b1 + l * 2048, nullptr, 2048, 2048, 512,  2048, 1);
        tf32gemm_kernel<<<gg(2048, 512),  256>>>(H,  lff_W2 + (size_t)l * 2048 * 512, X, lff_b2 + l * 512,  X,       2048, 512,  2048, 512,  0);
    }

    // ---- output head ----
    ln_kernel<<<NTOK, 256>>>(X, XN, out_norm_w, out_norm_b);
    tf32gemm_kernel<<<gg(2048, 32000), 256>>>(XN, out_W, (float*)d_out, out_b, nullptr,
                                              2048, 32000, 512, 32000, 0);
}

// round 5
// speedup vs baseline: 3.0253x; 1.1720x over previous
#include <cuda_runtime.h>
#include <math.h>
#include <stdint.h>

// ---------------- model constants ----------------
#define DMODEL 512
#define NTOK   2048
#define NWIN   16
#define WSZ    128
#define NHEAD  8
#define DHEAD  64
#define FFDIM  2048

// ---------------- scratch (no allocs allowed) ----------------
__device__ alignas(128) float g_X  [NTOK * DMODEL];
__device__ alignas(128) float g_XN [NTOK * DMODEL];
__device__ alignas(128) float g_Q  [NTOK * DMODEL];
__device__ alignas(128) float g_K  [NTOK * DMODEL];
__device__ alignas(128) float g_KVX[NTOK * 2 * DMODEL];
__device__ alignas(128) float g_H  [NTOK * FFDIM];
__device__ alignas(128) float g_AO [NTOK * DMODEL];
__device__ alignas(128) float g_G  [NWIN * DMODEL];
__device__ alignas(128) float g_GN [NWIN * DMODEL];
__device__ alignas(128) float g_QG [NWIN * DMODEL];
__device__ alignas(128) float g_KVG[NWIN * 2 * DMODEL];
__device__ alignas(128) float g_GO [NWIN * DMODEL];
__device__ alignas(128) float g_GH [NWIN * FFDIM];
__device__ alignas(128) float g_GKV[NWIN * 2 * DMODEL];
__device__ alignas(128) float g_WC [512 * 32000];   // tf32-converted weight staging

// ---------------- embedding gather ----------------
__global__ void embed_kernel(const int* __restrict__ tokens,
                             const float* __restrict__ emb,
                             float* __restrict__ X)
{
    int row = blockIdx.x;
    int d   = threadIdx.x;
    X[row * DMODEL + d] = emb[(size_t)tokens[row] * DMODEL + d];
}

// ---------------- window mean + pos emb ----------------
__global__ void winmean_kernel(const float* __restrict__ X,
                               const float* __restrict__ gpos,
                               float* __restrict__ G)
{
    int w = blockIdx.x;
    int d = threadIdx.x;
    float s = 0.f;
    for (int i = 0; i < WSZ; i++)
        s += X[(w * WSZ + i) * DMODEL + d];
    G[w * DMODEL + d] = s * (1.f / 128.f) + gpos[w * DMODEL + d];
}

// ---------------- layernorm ----------------
__global__ void ln_kernel(const float* __restrict__ in, float* __restrict__ out,
                          const float* __restrict__ w, const float* __restrict__ b)
{
    __shared__ float sh[8];
    __shared__ float stat;
    int row = blockIdx.x;
    int tid = threadIdx.x;
    const float* r = in + (size_t)row * DMODEL;
    float x0 = r[tid], x1 = r[tid + 256];

    float v = x0 + x1;
    for (int o = 16; o; o >>= 1) v += __shfl_down_sync(0xffffffffu, v, o);
    if ((tid & 31) == 0) sh[tid >> 5] = v;
    __syncthreads();
    if (tid == 0) {
        float t = 0.f;
        for (int i = 0; i < 8; i++) t += sh[i];
        stat = t * (1.f / 512.f);
    }
    __syncthreads();
    float mu = stat;
    float d0 = x0 - mu, d1 = x1 - mu;
    __syncthreads();
    v = d0 * d0 + d1 * d1;
    for (int o = 16; o; o >>= 1) v += __shfl_down_sync(0xffffffffu, v, o);
    if ((tid & 31) == 0) sh[tid >> 5] = v;
    __syncthreads();
    if (tid == 0) {
        float t = 0.f;
        for (int i = 0; i < 8; i++) t += sh[i];
        stat = t * (1.f / 512.f);
    }
    __syncthreads();
    float rstd = rsqrtf(stat + 1e-5f);
    out[(size_t)row * DMODEL + tid]       = d0 * rstd * w[tid]       + b[tid];
    out[(size_t)row * DMODEL + tid + 256] = d1 * rstd * w[tid + 256] + b[tid + 256];
}

// ---------------- tf32 helpers ----------------
__device__ __forceinline__ float to_tf32(float x)
{
    float r;
    asm("cvt.rna.tf32.f32 %0, %1;" : "=f"(r) : "f"(x));
    return r;
}

__device__ __forceinline__ void mma_tf32(float* c, const uint32_t* a, const uint32_t* b)
{
    asm volatile(
        "mma.sync.aligned.m16n8k8.row.col.f32.tf32.tf32.f32 "
        "{%0,%1,%2,%3}, {%4,%5,%6,%7}, {%8,%9}, {%0,%1,%2,%3};"
        : "+f"(c[0]), "+f"(c[1]), "+f"(c[2]), "+f"(c[3])
        : "r"(a[0]), "r"(a[1]), "r"(a[2]), "r"(a[3]), "r"(b[0]), "r"(b[1]));
}

__device__ __forceinline__ void cp_async16(uint32_t dst, const void* src)
{
    asm volatile("cp.async.ca.shared.global [%0], [%1], 16;" :: "r"(dst), "l"(src));
}
__device__ __forceinline__ void cp_commit() { asm volatile("cp.async.commit_group;"); }
__device__ __forceinline__ void cp_wait0()  { asm volatile("cp.async.wait_group 0;"); }

// ---------------- weight tf32 pre-convert (elementwise, n % 1024 == 0) ----------------
__global__ void tf32cvt_kernel(const float4* __restrict__ src, float4* __restrict__ dst)
{
    int i = blockIdx.x * 256 + threadIdx.x;
    float4 v = src[i];
    dst[i] = make_float4(to_tf32(v.x), to_tf32(v.y), to_tf32(v.z), to_tf32(v.w));
}

// ---------------- tf32 tensor-core GEMM (M%128==0, N%128==0, K%16==0) ----------------
// B must already be tf32-rounded (pre-converted). A is fp32, cvt'd in staging.
// A-smem: XOR-swizzled pair layout Asw[buf][g][row][8]: value (k'=c+4*hi, row r)
// at slot 2*(c^(r&3))+hi -> fragment (kc,kc+4) = one LDS.64, conflict-free.
// Staging applies the XOR to the STORE ADDRESS (4x STS.64), values statically indexed.
#define KT 16
#define SMS 136
__global__ void __launch_bounds__(256, 2) tf32gemm_kernel(
    const float* __restrict__ A, const float* __restrict__ B, float* __restrict__ C,
    const float* __restrict__ bias, const float* __restrict__ res,
    int M, int N, int K, int ldb, int gelu_flag)
{
    __shared__ float Asw[2][2][128][8];   // [buf][g][row][slot]
    __shared__ float Bs[2][KT][SMS];      // [buf][k][n]

    const int tid  = threadIdx.x;
    const int lane = tid & 31, warp = tid >> 5;
    const int wm = (warp & 1) * 64;
    const int wn = (warp >> 1) * 32;
    const int crow0 = blockIdx.y * 128, ccol0 = blockIdx.x * 128;

    const int a_r = tid >> 1, a_g = tid & 1;          // A: row, k-group
    const int a_r3 = a_r & 3;
    const int b_r = tid >> 4, b_c = (tid & 15) * 8;   // B: k, col

    const float* Ag = A + (size_t)(crow0 + a_r) * K + a_g * 8;
    const float* Bg = B + (size_t)b_r * ldb + ccol0 + b_c;

    const uint32_t bs0 = (uint32_t)__cvta_generic_to_shared(&Bs[0][b_r][b_c]);
    const uint32_t bs1 = (uint32_t)__cvta_generic_to_shared(&Bs[1][b_r][b_c]);

    const int r3q = (lane >> 2) & 3;
    const int so  = 2 * ((lane & 3) ^ r3q);           // fragment slot offset

    float acc[4][4][4];
#pragma unroll
    for (int i = 0; i < 4; i++)
#pragma unroll
        for (int j = 0; j < 4; j++)
#pragma unroll
            for (int k = 0; k < 4; k++) acc[i][j][k] = 0.f;

    const int nk = K / KT;

    // ---- stage tile 0 ----
    {
        float4 av0 = *reinterpret_cast<const float4*>(Ag);
        float4 av1 = *reinterpret_cast<const float4*>(Ag + 4);
        float* dst = &Asw[0][a_g][a_r][0];
        *reinterpret_cast<float2*>(dst + 2 * (0 ^ a_r3)) = make_float2(to_tf32(av0.x), to_tf32(av1.x));
        *reinterpret_cast<float2*>(dst + 2 * (1 ^ a_r3)) = make_float2(to_tf32(av0.y), to_tf32(av1.y));
        *reinterpret_cast<float2*>(dst + 2 * (2 ^ a_r3)) = make_float2(to_tf32(av0.z), to_tf32(av1.z));
        *reinterpret_cast<float2*>(dst + 2 * (3 ^ a_r3)) = make_float2(to_tf32(av0.w), to_tf32(av1.w));
        cp_async16(bs0,      Bg);
        cp_async16(bs0 + 16, Bg + 4);
        cp_commit();
    }
    cp_wait0();
    __syncthreads();

    for (int kt = 0; kt < nk; kt++) {
        const int cur = kt & 1, nxt = cur ^ 1;
        const bool more = (kt + 1 < nk);

        float4 av0, av1;
        if (more) {
            const float* Bp = Bg + (size_t)(kt + 1) * KT * ldb;
            uint32_t bsn = (nxt ? bs1 : bs0);
            cp_async16(bsn,      Bp);
            cp_async16(bsn + 16, Bp + 4);
            cp_commit();
            const float* Ap = Ag + (kt + 1) * KT;
            av0 = *reinterpret_cast<const float4*>(Ap);
            av1 = *reinterpret_cast<const float4*>(Ap + 4);
        }

#pragma unroll
        for (int kk = 0; kk < KT; kk += 8) {
            const int g = kk >> 3;
            uint32_t af[4][4], bf[4][2];
            const int kc = kk + (lane & 3);
#pragma unroll
            for (int am = 0; am < 4; am++) {
                const int r = wm + am * 16 + (lane >> 2);
                float2 p0 = *reinterpret_cast<const float2*>(&Asw[cur][g][r][so]);
                float2 p1 = *reinterpret_cast<const float2*>(&Asw[cur][g][r + 8][so]);
                af[am][0] = __float_as_uint(p0.x);
                af[am][1] = __float_as_uint(p1.x);
                af[am][2] = __float_as_uint(p0.y);
                af[am][3] = __float_as_uint(p1.y);
            }
#pragma unroll
            for (int bn = 0; bn < 4; bn++) {
                const int cc = wn + bn * 8 + (lane >> 2);
                bf[bn][0] = __float_as_uint(Bs[cur][kc][cc]);
                bf[bn][1] = __float_as_uint(Bs[cur][kc + 4][cc]);
            }
#pragma unroll
            for (int am = 0; am < 4; am++)
#pragma unroll
                for (int bn = 0; bn < 4; bn++)
                    mma_tf32(acc[am][bn], af[am], bf[bn]);
        }

        if (more) {
            float* dst = &Asw[nxt][a_g][a_r][0];
            *reinterpret_cast<float2*>(dst + 2 * (0 ^ a_r3)) = make_float2(to_tf32(av0.x), to_tf32(av1.x));
            *reinterpret_cast<float2*>(dst + 2 * (1 ^ a_r3)) = make_float2(to_tf32(av0.y), to_tf32(av1.y));
            *reinterpret_cast<float2*>(dst + 2 * (2 ^ a_r3)) = make_float2(to_tf32(av0.z), to_tf32(av1.z));
            *reinterpret_cast<float2*>(dst + 2 * (3 ^ a_r3)) = make_float2(to_tf32(av0.w), to_tf32(av1.w));
            cp_wait0();
            __syncthreads();
        }
    }

    // ---- epilogue ----
#pragma unroll
    for (int am = 0; am < 4; am++) {
        const int r0 = crow0 + wm + am * 16 + (lane >> 2);
#pragma unroll
        for (int bn = 0; bn < 4; bn++) {
            const int c0 = ccol0 + wn + bn * 8 + (lane & 3) * 2;
            float v0 = acc[am][bn][0], v1 = acc[am][bn][1];
            float v2 = acc[am][bn][2], v3 = acc[am][bn][3];
            if (bias) {
                float b0 = bias[c0], b1 = bias[c0 + 1];
                v0 += b0; v1 += b1; v2 += b0; v3 += b1;
            }
            if (gelu_flag) {
                v0 = 0.5f * v0 * (1.f + erff(v0 * 0.70710678118654752f));
                v1 = 0.5f * v1 * (1.f + erff(v1 * 0.70710678118654752f));
                v2 = 0.5f * v2 * (1.f + erff(v2 * 0.70710678118654752f));
                v3 = 0.5f * v3 * (1.f + erff(v3 * 0.70710678118654752f));
            }
            size_t i0 = (size_t)r0 * N + c0;
            size_t i1 = (size_t)(r0 + 8) * N + c0;
            if (res) {
                v0 += res[i0]; v1 += res[i0 + 1];
                v2 += res[i1]; v3 += res[i1 + 1];
            }
            *reinterpret_cast<float2*>(C + i0) = make_float2(v0, v1);
            *reinterpret_cast<float2*>(C + i1) = make_float2(v2, v3);
        }
    }
}

// ---------------- small-M GEMM (M<=16), fp32, split-K within block ----------------
#define SG_KC 256
__global__ void __launch_bounds__(1024, 1) smallgemm_kernel(
    const float* __restrict__ A, const float* __restrict__ B, float* __restrict__ C,
    const float* __restrict__ bias, const float* __restrict__ res,
    int M, int N, int K, int ldb, int gelu_flag)
{
    __shared__ float As[2][16][SG_KC];   // [half][row][k]
    __shared__ float Ps[16][128];        // upper-half partials
    const int tid  = threadIdx.x;
    const int col  = blockIdx.x * 128 + (tid & 127);
    const int grp  = tid >> 7;           // 0..7
    const int half = grp >> 2;           // 0,1
    const int rg   = grp & 3;            // row group
    const int Kh   = K >> 1;

    float acc[4] = {0.f, 0.f, 0.f, 0.f};
    const float* Bp = B + (size_t)half * Kh * ldb + col;

    for (int kc = 0; kc < Kh; kc += SG_KC) {
        for (int idx = tid; idx < 2 * 16 * SG_KC; idx += 1024) {
            int h = idx >> 12;
            int r = (idx >> 8) & 15;
            int k = idx & (SG_KC - 1);
            As[h][r][k] = (r < M) ? A[(size_t)r * K + h * Kh + kc + k] : 0.f;
        }
        __syncthreads();
#pragma unroll 1
        for (int k0 = 0; k0 < SG_KC; k0 += 16) {
            float bv[16];
#pragma unroll
            for (int u = 0; u < 16; u++)
                bv[u] = Bp[(size_t)(kc + k0 + u) * ldb];
#pragma unroll
            for (int u = 0; u < 16; u++) {
#pragma unroll
                for (int r = 0; r < 4; r++)
                    acc[r] = fmaf(As[half][rg * 4 + r][k0 + u], bv[u], acc[r]);
            }
        }
        __syncthreads();
    }

    if (half == 1) {
#pragma unroll
        for (int r = 0; r < 4; r++)
            Ps[rg * 4 + r][tid & 127] = acc[r];
    }
    __syncthreads();
    if (half == 0) {
#pragma unroll
        for (int r = 0; r < 4; r++) {
            int gr = rg * 4 + r;
            if (gr >= M) continue;
            float v = acc[r] + Ps[gr][tid & 127];
            if (bias) v += bias[col];
            if (gelu_flag) v = 0.5f * v * (1.f + erff(v * 0.70710678118654752f));
            size_t idx = (size_t)gr * N + col;
            if (res) v += res[idx];
            C[idx] = v;
        }
    }
}

// ---------------- rotary embedding ----------------
__global__ void rotary_kernel(float* __restrict__ Q, float* __restrict__ K)
{
    int i = blockIdx.x;
    int t = threadIdx.x;
    int h = t >> 5, d = t & 31;
    float inv = 1.f / powf(10000.f, (float)(2 * d) / 64.f);
    float ang = (float)i * inv;
    float s, c;
    sincosf(ang, &s, &c);
    int base = i * DMODEL + h * DHEAD + d;
    float a = Q[base], b2 = Q[base + 32];
    Q[base]      = a * c - b2 * s;
    Q[base + 32] = b2 * c + a * s;
    a = K[base]; b2 = K[base + 32];
    K[base]      = a * c - b2 * s;
    K[base + 32] = b2 * c + a * s;
}

// ---------------- global-token attention ----------------
__global__ void global_attn_kernel(const float* __restrict__ QG,
                                   const float* __restrict__ KVG,
                                   const float* __restrict__ KVX,
                                   float* __restrict__ GO)
{
    __shared__ float q[64];
    __shared__ float lg[129];
    int w = blockIdx.x, h = blockIdx.y;
    int tid = threadIdx.x;
    if (tid < 64) q[tid] = QG[w * DMODEL + h * DHEAD + tid];
    __syncthreads();
    if (tid < 129) {
        const float* kp = (tid == 0)
            ? (KVG + (size_t)w * 1024 + h * DHEAD)
            : (KVX + (size_t)(w * WSZ + tid - 1) * 1024 + h * DHEAD);
        float dt = 0.f;
#pragma unroll
        for (int d = 0; d < 64; d++) dt = fmaf(q[d], kp[d], dt);
        lg[tid] = dt * 0.125f;
    }
    __syncthreads();
    float m = -1e30f;
    for (int j = 0; j < 129; j++) m = fmaxf(m, lg[j]);
    float s = 0.f;
    for (int j = 0; j < 129; j++) s += expf(lg[j] - m);
    if (tid < 64) {
        float acc = 0.f;
        for (int j = 0; j < 129; j++) {
            float p = expf(lg[j] - m);
            float v = (j == 0)
                ? KVG[(size_t)w * 1024 + 512 + h * DHEAD + tid]
                : KVX[(size_t)(w * WSZ + j - 1) * 1024 + 512 + h * DHEAD + tid];
            acc = fmaf(p, v, acc);
        }
        GO[w * DMODEL + h * DHEAD + tid] = acc / s;
    }
}

// ---------------- local windowed attention ----------------
__global__ void local_attn_kernel(const float* __restrict__ Q,
                                  const float* __restrict__ K,
                                  const float* __restrict__ GKV,
                                  float* __restrict__ AO)
{
    extern __shared__ float sm[];
    float* sk  = sm;                 // [271][64]
    float* sgv = sm + 271 * 64;      // [15][64]
    int w = blockIdx.x, h = blockIdx.y;
    int tid = threadIdx.x;           // 128

    for (int idx = tid; idx < 15 * 64; idx += 128) {
        int j = idx >> 6, d = idx & 63;
        sk[idx]  = GKV[(size_t)j * 1024 + h * DHEAD + d];
        sgv[idx] = GKV[(size_t)j * 1024 + 512 + h * DHEAD + d];
    }
    for (int idx = tid; idx < 256 * 64; idx += 128) {
        int c = idx >> 6, d = idx & 63;
        int t = (w - 1) * WSZ + c;
        sk[15 * 64 + idx] = (t >= 0) ? K[(size_t)t * DMODEL + h * DHEAD + d] : 0.f;
    }
    __syncthreads();

    const int i = tid;
    float q[64];
    const float* qp = Q + (size_t)(w * WSZ + i) * DMODEL + h * DHEAD;
#pragma unroll
    for (int d = 0; d < 64; d++) q[d] = qp[d];

    const int jend = 15 + i + 128;

    float m = -1e30f;
    for (int j = 0; j < w; j++) {
        const float* kp = sk + j * 64;
        float dt = 0.f;
#pragma unroll
        for (int d = 0; d < 64; d++) dt = fmaf(q[d], kp[d], dt);
        m = fmaxf(m, dt * 0.125f);
    }
    for (int j = 15; j <= jend; j++) {
        const float* kp = sk + j * 64;
        float dt = 0.f;
#pragma unroll
        for (int d = 0; d < 64; d++) dt = fmaf(q[d], kp[d], dt);
        m = fmaxf(m, dt * 0.125f);
    }

    float s = 0.f;
    float acc[64];
#pragma unroll
    for (int d = 0; d < 64; d++) acc[d] = 0.f;
    for (int j = 0; j < w; j++) {
        const float* kp = sk + j * 64;
        float dt = 0.f;
#pragma unroll
        for (int d = 0; d < 64; d++) dt = fmaf(q[d], kp[d], dt);
        float e = expf(dt * 0.125f - m);
        s += e;
        const float* vp = sgv + j * 64;
#pragma unroll
        for (int d = 0; d < 64; d++) acc[d] = fmaf(e, vp[d], acc[d]);
    }
    for (int j = 15; j <= jend; j++) {
        const float* kp = sk + j * 64;
        float dt = 0.f;
#pragma unroll
        for (int d = 0; d < 64; d++) dt = fmaf(q[d], kp[d], dt);
        float e = expf(dt * 0.125f - m);
        s += e;
#pragma unroll
        for (int d = 0; d < 64; d++) acc[d] = fmaf(e, kp[d], acc[d]);
    }
    float inv = 1.f / s;
    float* op = AO + (size_t)(w * WSZ + i) * DMODEL + h * DHEAD;
#pragma unroll
    for (int d = 0; d < 64; d++) op[d] = acc[d] * inv;
}

// ---------------- host orchestration ----------------
static inline dim3 gg(int M, int N) { return dim3(N / 128, (M + 127) / 128); }

extern "C" void kernel_launch(void* const* d_in, const int* in_sizes, int n_in,
                              void* d_out, int out_size)
{
    const int*   tokens     = (const int*)  d_in[0];
    const float* tok_emb    = (const float*)d_in[1];
    const float* gpos_emb   = (const float*)d_in[2];
    const float* g_norm_w   = (const float*)d_in[3];
    const float* g_norm_b   = (const float*)d_in[4];
    const float* g_Wq       = (const float*)d_in[5];
    const float* g_Wkv      = (const float*)d_in[6];
    const float* g_Wo       = (const float*)d_in[7];
    const float* g_bo       = (const float*)d_in[8];
    const float* gff_norm_w = (const float*)d_in[9];
    const float* gff_norm_b = (const float*)d_in[10];
    const float* gff_W1     = (const float*)d_in[11];
    const float* gff_b1     = (const float*)d_in[12];
    const float* gff_W2     = (const float*)d_in[13];
    const float* gff_b2     = (const float*)d_in[14];
    const float* la_norm_w  = (const float*)d_in[15];
    const float* la_norm_b  = (const float*)d_in[16];
    const float* la_Wq      = (const float*)d_in[17];
    const float* la_Wkv     = (const float*)d_in[18];
    const float* la_Wo      = (const float*)d_in[19];
    const float* la_bo      = (const float*)d_in[20];
    const float* lff_norm_w = (const float*)d_in[21];
    const float* lff_norm_b = (const float*)d_in[22];
    const float* lff_W1     = (const float*)d_in[23];
    const float* lff_b1     = (const float*)d_in[24];
    const float* lff_W2     = (const float*)d_in[25];
    const float* lff_b2     = (const float*)d_in[26];
    const float* out_norm_w = (const float*)d_in[27];
    const float* out_norm_b = (const float*)d_in[28];
    const float* out_W      = (const float*)d_in[29];
    const float* out_b      = (const float*)d_in[30];

    float *X, *XN, *Q, *K, *KVX, *H, *AO, *G, *GN, *QG, *KVG, *GO, *GH, *GKV, *WC;
    cudaGetSymbolAddress((void**)&X,   g_X);
    cudaGetSymbolAddress((void**)&XN,  g_XN);
    cudaGetSymbolAddress((void**)&Q,   g_Q);
    cudaGetSymbolAddress((void**)&K,   g_K);
    cudaGetSymbolAddress((void**)&KVX, g_KVX);
    cudaGetSymbolAddress((void**)&H,   g_H);
    cudaGetSymbolAddress((void**)&AO,  g_AO);
    cudaGetSymbolAddress((void**)&G,   g_G);
    cudaGetSymbolAddress((void**)&GN,  g_GN);
    cudaGetSymbolAddress((void**)&QG,  g_QG);
    cudaGetSymbolAddress((void**)&KVG, g_KVG);
    cudaGetSymbolAddress((void**)&GO,  g_GO);
    cudaGetSymbolAddress((void**)&GH,  g_GH);
    cudaGetSymbolAddress((void**)&GKV, g_GKV);
    cudaGetSymbolAddress((void**)&WC,  g_WC);

    cudaFuncSetAttribute(local_attn_kernel,
                         cudaFuncAttributeMaxDynamicSharedMemorySize, 73216);

    // converted-weight region pointers (disjoint slices of g_WC, reused per layer)
    float* WC_kvx = WC;                    // 512*1024
    float* WC_q   = WC + 512 * 1024;       // 512*512
    float* WC_kv  = WC + 512 * 1536;       // 512*1024
    float* WC_wo  = WC + 512 * 2560;       // 512*512
    float* WC_ff1 = WC + 512 * 3072;       // 512*2048
    float* WC_ff2 = WC + 512 * 5120;       // 2048*512
    // head weight conversion also reuses WC from offset 0 (after layer GEMMs done)

#define CVT(dst, src, n) tf32cvt_kernel<<<(n) / 1024, 256>>>((const float4*)(src), (float4*)(dst))

    embed_kernel<<<NTOK, DMODEL>>>(tokens, tok_emb, X);
    winmean_kernel<<<NWIN, DMODEL>>>(X, gpos_emb, G);
    CVT(WC_kvx, g_Wkv, 512 * 1024);        // shared across layers, converted once

    for (int l = 0; l < 2; l++) {
        // ---- global-token transformer (shared weights) ----
        ln_kernel<<<NWIN, 256>>>(G, GN, g_norm_w, g_norm_b);
        tf32gemm_kernel<<<gg(2048, 1024), 256>>>(X, WC_kvx, KVX, nullptr, nullptr, 2048, 1024, 512, 1024, 0);
        smallgemm_kernel<<<4,  1024>>>(GN, g_Wq,  QG,  nullptr, nullptr, 16, 512,  512, 512,  0);
        smallgemm_kernel<<<8,  1024>>>(GN, g_Wkv, KVG, nullptr, nullptr, 16, 1024, 512, 1024, 0);
        global_attn_kernel<<<dim3(16, 8), 256>>>(QG, KVG, KVX, GO);
        smallgemm_kernel<<<4,  1024>>>(GO, g_Wo, G, g_bo, G, 16, 512, 512, 512, 0);
        ln_kernel<<<NWIN, 256>>>(G, GN, gff_norm_w, gff_norm_b);
        smallgemm_kernel<<<16, 1024>>>(GN, gff_W1, GH, gff_b1, nullptr, 16, 2048, 512,  2048, 1);
        smallgemm_kernel<<<4,  1024>>>(GH, gff_W2, G,  gff_b2, G,       16, 512,  2048, 512,  0);

        // ---- local windowed attention ----
        CVT(WC_q,  la_Wq  + (size_t)l * 512 * 512,  512 * 512);
        CVT(WC_kv, la_Wkv + (size_t)l * 512 * 1024, 512 * 1024);
        CVT(WC_wo, la_Wo  + (size_t)l * 512 * 512,  512 * 512);
        ln_kernel<<<NTOK, 256>>>(X, XN, la_norm_w + l * 512, la_norm_b + l * 512);
        tf32gemm_kernel<<<gg(2048, 512), 256>>>(XN, WC_q,  Q, nullptr, nullptr, 2048, 512, 512, 512,  0);
        tf32gemm_kernel<<<gg(2048, 512), 256>>>(XN, WC_kv, K, nullptr, nullptr, 2048, 512, 512, 1024, 0);
        smallgemm_kernel<<<8, 1024>>>(G, la_Wkv + (size_t)l * 512 * 1024, GKV, nullptr, nullptr, 15, 1024, 512, 1024, 0);
        rotary_kernel<<<NTOK, 256>>>(Q, K);
        local_attn_kernel<<<dim3(16, 8), 128, 73216>>>(Q, K, GKV, AO);
        tf32gemm_kernel<<<gg(2048, 512), 256>>>(AO, WC_wo, X, la_bo + l * 512, X, 2048, 512, 512, 512, 0);

        // ---- local FF ----
        CVT(WC_ff1, lff_W1 + (size_t)l * 512 * 2048, 512 * 2048);
        CVT(WC_ff2, lff_W2 + (size_t)l * 2048 * 512, 2048 * 512);
        ln_kernel<<<NTOK, 256>>>(X, XN, lff_norm_w + l * 512, lff_norm_b + l * 512);
        tf32gemm_kernel<<<gg(2048, 2048), 256>>>(XN, WC_ff1, H, lff_b1 + l * 2048, nullptr, 2048, 2048, 512,  2048, 1);
        tf32gemm_kernel<<<gg(2048, 512),  256>>>(H,  WC_ff2, X, lff_b2 + l * 512,  X,       2048, 512,  2048, 512,  0);
    }

    // ---- output head ----
    CVT(WC, out_W, 512 * 32000);
    ln_kernel<<<NTOK, 256>>>(X, XN, out_norm_w, out_norm_b);
    tf32gemm_kernel<<<gg(2048, 32000), 256>>>(XN, WC, (float*)d_out, out_b, nullptr,
                                              2048, 32000, 512, 32000, 0);
}